// round 15
// baseline (speedup 1.0000x reference)
#include <cuda_runtime.h>
#include <math.h>
#include <stdint.h>

#define Bn 256
#define Ldim 64
#define Sn 12
#define Dn 100
#define NUM_NODE 43098
#define NOUT 43097
#define NEGV -9000000000000000.0f
#define NCHUNK 8
#define CHUNKSZ 5388   // ceil(43097/8)

// ---------------- scratch (device globals; no allocation) ----------------
__device__ float g_h[Bn*Ldim*Dn];
__device__ float g_hlocal[Bn*Ldim*Dn];
__device__ float g_nb[Bn*Ldim*Dn];
__device__ float g_hcomb[Bn*Ldim*Dn];
__device__ float g_seq[Bn*Ldim*Dn];
__device__ float g_hsg[Bn*Dn];
__device__ float g_selpart[2*Bn*Dn];
__device__ unsigned g_rmaxbits[Bn];
__device__ float g_rpart[Bn*NCHUNK];

__device__ __forceinline__ unsigned fkey(float f) {
    unsigned u = __float_as_uint(f);
    return (u & 0x80000000u) ? ~u : (u | 0x80000000u);
}
__device__ __forceinline__ float funkey(unsigned k) {
    return (k & 0x80000000u) ? __uint_as_float(k ^ 0x80000000u)
                             : __uint_as_float(~k);
}

__device__ __forceinline__ float fexp(float x) {
    float y = x * 1.44269504088896340736f;
    y = fmaxf(y, -126.0f);
    float t = y + 12582912.0f;
    float i = t - 12582912.0f;
    float f = y - i;
    int ii = (int)i;
    float p = 1.54035303933816e-4f;
    p = fmaf(p, f, 1.33335581464284e-3f);
    p = fmaf(p, f, 9.61812910762848e-3f);
    p = fmaf(p, f, 5.55041086648216e-2f);
    p = fmaf(p, f, 2.40226506959101e-1f);
    p = fmaf(p, f, 6.93147180559945e-1f);
    p = fmaf(p, f, 1.0f);
    return p * __int_as_float((ii + 127) << 23);
}

__device__ __forceinline__ float to_tf32(float x) {
    uint32_t r;
    asm("cvt.rna.tf32.f32 %0, %1;" : "=r"(r) : "f"(x));
    return __uint_as_float(r);
}

// ---------------- K0 ----------------
__global__ void k_init() {
    int t = threadIdx.x;
    if (t < Bn) g_rmaxbits[t] = 0u;
}

// ---------------- K1: local graph attention (float4, 2 CTAs/row) -----------
__global__ __launch_bounds__(256) void k_local(
    const int* __restrict__ items, const int* __restrict__ adj,
    const float* __restrict__ emb,
    const float* __restrict__ a0, const float* __restrict__ a1,
    const float* __restrict__ a2, const float* __restrict__ a3)
{
    int b = blockIdx.x >> 1;
    int half = blockIdx.x & 1;
    int i0 = half * 32;
    __shared__ float hs[Ldim][108];
    __shared__ float alpha[32][Ldim+1];
    __shared__ float At[4][108];
    int tid = threadIdx.x;

    for (int i = tid; i < Dn; i += 256) {
        At[0][i] = a0[i]; At[1][i] = a1[i]; At[2][i] = a2[i]; At[3][i] = a3[i];
    }
    for (int idx = tid; idx < Ldim*25; idx += 256) {
        int l = idx / 25, c4 = (idx % 25) * 4;
        float4 v = *(const float4*)(emb + (size_t)items[b*Ldim + l]*Dn + c4);
        *(float4*)(&hs[l][c4]) = v;
    }
    __syncthreads();
    for (int idx = tid; idx < 32*25; idx += 256) {
        int l = i0 + idx / 25, c4 = (idx % 25) * 4;
        *(float4*)(g_h + ((size_t)b*Ldim + l)*Dn + c4) = *(const float4*)(&hs[l][c4]);
    }

    for (int p = tid; p < 32*Ldim; p += 256) {
        int il = p >> 6, j = p & 63;
        int i = i0 + il;
        int a = adj[((size_t)b*Ldim + i)*Ldim + j];
        float val = NEGV;
        if (a >= 1 && a <= 4) {
            int k = a - 1;
            const float4* hi = (const float4*)hs[i];
            const float4* hj = (const float4*)hs[j];
            const float4* at = (const float4*)At[k];
            float acc = 0.f;
            #pragma unroll 5
            for (int d4 = 0; d4 < 25; d4++) {
                float4 x = hi[d4], y = hj[d4], w = at[d4];
                acc = fmaf(x.x*y.x, w.x, acc);
                acc = fmaf(x.y*y.y, w.y, acc);
                acc = fmaf(x.z*y.z, w.z, acc);
                acc = fmaf(x.w*y.w, w.w, acc);
            }
            val = acc > 0.f ? acc : 0.2f * acc;
        }
        alpha[il][j] = val;
    }
    __syncthreads();

    int warp = tid >> 5, lane = tid & 31;
    for (int il = warp; il < 32; il += 8) {
        float x0 = alpha[il][lane], x1 = alpha[il][lane+32];
        float m = fmaxf(x0, x1);
        #pragma unroll
        for (int o = 16; o > 0; o >>= 1) m = fmaxf(m, __shfl_xor_sync(0xffffffffu, m, o));
        float e0 = __expf(fmaxf(x0 - m, -87.f));
        float e1 = __expf(fmaxf(x1 - m, -87.f));
        float s = e0 + e1;
        #pragma unroll
        for (int o = 16; o > 0; o >>= 1) s += __shfl_xor_sync(0xffffffffu, s, o);
        float inv = 1.f / s;
        alpha[il][lane] = e0 * inv;
        alpha[il][lane+32] = e1 * inv;
    }
    __syncthreads();

    for (int idx = tid; idx < 32*25; idx += 256) {
        int il = idx / 25, c4 = (idx % 25) * 4;
        float ax = 0.f, ay = 0.f, az = 0.f, aw = 0.f;
        for (int j = 0; j < Ldim; j++) {
            float al = alpha[il][j];
            float4 v = *(const float4*)(&hs[j][c4]);
            ax = fmaf(al, v.x, ax);
            ay = fmaf(al, v.y, ay);
            az = fmaf(al, v.z, az);
            aw = fmaf(al, v.w, aw);
        }
        *(float4*)(g_hlocal + ((size_t)b*Ldim + i0 + il)*Dn + c4)
            = make_float4(ax, ay, az, aw);
    }
}

// ---------------- K3: global neighbor aggregation (tf32 mma; in-CTA sess) --
#define GT_W1   0        // 104*104 = 10816
#define GT_FEAT 10816    // 96*108  = 10368
#define GT_W2   21184    // 104
#define GT_SESS 21288    // 100
#define GT_ALSC 21388    // 96
#define GT_NBR  21484    // 96 ints
#define GT_TOT  21580
__global__ __launch_bounds__(256, 2) void k_global(
    const int* __restrict__ items, const int* __restrict__ adj_all,
    const float* __restrict__ num_w, const float* __restrict__ emb,
    const float* __restrict__ g_w1, const float* __restrict__ g_w2,
    const int* __restrict__ seq_features, const float* __restrict__ mask)
{
    extern __shared__ float sm[];
    float* w1s   = sm + GT_W1;
    float* feat  = sm + GT_FEAT;
    float* w2s   = sm + GT_W2;
    float* sesss = sm + GT_SESS;
    float* alsc  = sm + GT_ALSC;
    int*   nbrs  = (int*)(sm + GT_NBR);

    int blk = blockIdx.x;
    int b = blk >> 1;
    int l0 = (blk & 1) * 32;
    int tid = threadIdx.x;
    int lane = tid & 31, warp = tid >> 5;

    for (int i = tid; i < 104*104; i += 256) w1s[i] = 0.f;
    if (tid < 104) w2s[tid] = (tid < Dn) ? g_w2[tid] : 0.f;
    if (tid < Ldim) alsc[tid] = mask[b*Ldim + tid];
    for (int idx = tid; idx < Ldim*25; idx += 256) {
        int r = idx / 25, c4 = (idx % 25) * 4;
        float4 v = *(const float4*)(emb + (size_t)seq_features[b*Ldim + r]*Dn + c4);
        *(float4*)(feat + r*108 + c4) = v;
    }
    __syncthreads();
    if (tid < Dn) {
        float s = 0.f, ms = 0.f;
        for (int l = 0; l < Ldim; l++) {
            s = fmaf(feat[l*108 + tid], alsc[l], s);
            ms += alsc[l];
        }
        sesss[tid] = s / ms;
    }
    __syncthreads();
    for (int i = tid; i < 101*100; i += 256) {
        int k = i / 100, n = i % 100;
        float scale = (k < 100) ? sesss[k] : 1.f;
        w1s[k*104 + n] = to_tf32(g_w1[i] * scale);
    }
    __syncthreads();

    int g = lane >> 2, tg = lane & 3;

    for (int it = 0; it < 4; it++) {
        int lbase = l0 + it*8;
        if (tid < 96) {
            int l = tid / 12, s = tid % 12;
            int node = items[b*Ldim + lbase + l];
            nbrs[tid] = adj_all[(size_t)node*Sn + s];
            feat[tid*108 + 100] = to_tf32(num_w[(size_t)node*Sn + s]);
            feat[tid*108 + 101] = 0.f;
            feat[tid*108 + 102] = 0.f;
            feat[tid*108 + 103] = 0.f;
        }
        for (int idx = tid; idx < 96*25; idx += 256) {
            int r = idx / 25, c4 = (idx % 25) * 4;
            int node = items[b*Ldim + lbase + r/12];
            int nbr  = adj_all[(size_t)node*Sn + (r%12)];
            float4 e = *(const float4*)(emb + (size_t)nbr*Dn + c4);
            float* dst = feat + r*108 + c4;
            dst[0] = to_tf32(e.x);
            dst[1] = to_tf32(e.y);
            dst[2] = to_tf32(e.z);
            dst[3] = to_tf32(e.w);
        }
        __syncthreads();

        if (warp < 6) {
            const float* Ab = feat + warp*16*108;
            float acc[13][4];
            #pragma unroll
            for (int nt = 0; nt < 13; nt++)
                #pragma unroll
                for (int q = 0; q < 4; q++) acc[nt][q] = 0.f;

            #pragma unroll 1
            for (int kt = 0; kt < 13; kt++) {
                int ak = kt*8;
                uint32_t a0 = __float_as_uint(Ab[ g   *108 + ak + tg    ]);
                uint32_t a1 = __float_as_uint(Ab[(g+8)*108 + ak + tg    ]);
                uint32_t a2 = __float_as_uint(Ab[ g   *108 + ak + tg + 4]);
                uint32_t a3 = __float_as_uint(Ab[(g+8)*108 + ak + tg + 4]);
                const float* wrow0 = w1s + (ak + tg)*104;
                const float* wrow1 = w1s + (ak + tg + 4)*104;
                #pragma unroll
                for (int nt = 0; nt < 13; nt++) {
                    uint32_t b0 = __float_as_uint(wrow0[nt*8 + g]);
                    uint32_t b1 = __float_as_uint(wrow1[nt*8 + g]);
                    asm volatile(
                        "mma.sync.aligned.m16n8k8.row.col.f32.tf32.tf32.f32 "
                        "{%0,%1,%2,%3}, {%4,%5,%6,%7}, {%8,%9}, {%0,%1,%2,%3};"
                        : "+f"(acc[nt][0]), "+f"(acc[nt][1]), "+f"(acc[nt][2]), "+f"(acc[nt][3])
                        : "r"(a0), "r"(a1), "r"(a2), "r"(a3), "r"(b0), "r"(b1));
                }
            }

            float score_a = 0.f, score_b = 0.f;
            #pragma unroll
            for (int nt = 0; nt < 13; nt++) {
                int j0 = nt*8 + tg*2;
                float w20 = w2s[j0], w21 = w2s[j0+1];
                float v0 = acc[nt][0] > 0.f ? acc[nt][0] : 0.2f*acc[nt][0];
                float v1 = acc[nt][1] > 0.f ? acc[nt][1] : 0.2f*acc[nt][1];
                float v2 = acc[nt][2] > 0.f ? acc[nt][2] : 0.2f*acc[nt][2];
                float v3 = acc[nt][3] > 0.f ? acc[nt][3] : 0.2f*acc[nt][3];
                score_a = fmaf(v0, w20, fmaf(v1, w21, score_a));
                score_b = fmaf(v2, w20, fmaf(v3, w21, score_b));
            }
            score_a += __shfl_xor_sync(0xffffffffu, score_a, 1);
            score_a += __shfl_xor_sync(0xffffffffu, score_a, 2);
            score_b += __shfl_xor_sync(0xffffffffu, score_b, 1);
            score_b += __shfl_xor_sync(0xffffffffu, score_b, 2);
            if (tg == 0) {
                alsc[warp*16 + g]     = score_a;
                alsc[warp*16 + g + 8] = score_b;
            }
        }
        __syncthreads();

        if (tid < 8) {
            float* a = alsc + tid*12;
            float m = a[0];
            #pragma unroll
            for (int s = 1; s < Sn; s++) m = fmaxf(m, a[s]);
            float ssum = 0.f;
            float e[Sn];
            #pragma unroll
            for (int s = 0; s < Sn; s++) { e[s] = __expf(a[s] - m); ssum += e[s]; }
            float inv = 1.f / ssum;
            #pragma unroll
            for (int s = 0; s < Sn; s++) a[s] = e[s] * inv;
        }
        __syncthreads();

        for (int idx = tid; idx < 800; idx += 256) {
            int l = idx / 100, c = idx % 100;
            const float* fr = feat + (l*12)*108 + c;
            const float* al = alsc + l*12;
            float acc2 = 0.f;
            #pragma unroll
            for (int s = 0; s < Sn; s++)
                acc2 = fmaf(al[s], fr[s*108], acc2);
            g_nb[((size_t)b*Ldim + lbase + l)*Dn + c] = acc2;
        }
        __syncthreads();
    }
}

// ---------------- K4: h_combine (tf32 mma, chunked w3, grid 512) ------------
#define CB_W3C 0             // 104*104 = 10816
#define CB_INS 10816         // 32*204  = 6528
#define CB_TOT 17344
__global__ __launch_bounds__(256) void k_combine(const float* __restrict__ g_w3)
{
    extern __shared__ float sm[];
    float* w3c = sm + CB_W3C;
    float* ins = sm + CB_INS;
    int tid = threadIdx.x;
    int lane = tid & 31, warp = tid >> 5;
    int row0 = blockIdx.x * 32;

    for (int idx = tid; idx < 32*25; idx += 256) {
        int r = idx / 25, c4 = (idx % 25) * 4;
        size_t row = row0 + r;
        float4 vh = *(const float4*)(g_h  + row*Dn + c4);
        float4 vn = *(const float4*)(g_nb + row*Dn + c4);
        float* d = ins + r*204;
        d[c4+0]   = to_tf32(vh.x); d[c4+1]   = to_tf32(vh.y);
        d[c4+2]   = to_tf32(vh.z); d[c4+3]   = to_tf32(vh.w);
        d[100+c4+0] = to_tf32(vn.x); d[100+c4+1] = to_tf32(vn.y);
        d[100+c4+2] = to_tf32(vn.z); d[100+c4+3] = to_tf32(vn.w);
    }
    if (tid < 32) {
        float* d = ins + tid*204 + 200;
        d[0] = 0.f; d[1] = 0.f; d[2] = 0.f; d[3] = 0.f;
    }
    // chunk 0: k rows 0..95
    for (int i = tid; i < 96*104; i += 256) {
        int k = i / 104, n = i % 104;
        w3c[i] = (n < 100) ? to_tf32(g_w3[k*100 + n]) : 0.f;
    }
    __syncthreads();

    int g = lane >> 2, tg = lane & 3;
    int mt = warp & 1;
    int ng = warp >> 1;

    float acc[4][4];
    #pragma unroll
    for (int j = 0; j < 4; j++)
        #pragma unroll
        for (int q = 0; q < 4; q++) acc[j][q] = 0.f;

    const float* Arow = ins + mt*16*204;
    #pragma unroll 1
    for (int kt = 0; kt < 12; kt++) {
        int ak = kt*8;
        uint32_t a0 = __float_as_uint(Arow[ g   *204 + ak + tg    ]);
        uint32_t a1 = __float_as_uint(Arow[(g+8)*204 + ak + tg    ]);
        uint32_t a2 = __float_as_uint(Arow[ g   *204 + ak + tg + 4]);
        uint32_t a3 = __float_as_uint(Arow[(g+8)*204 + ak + tg + 4]);
        #pragma unroll
        for (int j = 0; j < 4; j++) {
            int nt = ng*4 + j;
            if (nt < 13) {
                uint32_t b0 = __float_as_uint(w3c[(ak + tg    )*104 + nt*8 + g]);
                uint32_t b1 = __float_as_uint(w3c[(ak + tg + 4)*104 + nt*8 + g]);
                asm volatile(
                    "mma.sync.aligned.m16n8k8.row.col.f32.tf32.tf32.f32 "
                    "{%0,%1,%2,%3}, {%4,%5,%6,%7}, {%8,%9}, {%0,%1,%2,%3};"
                    : "+f"(acc[j][0]), "+f"(acc[j][1]), "+f"(acc[j][2]), "+f"(acc[j][3])
                    : "r"(a0), "r"(a1), "r"(a2), "r"(a3), "r"(b0), "r"(b1));
            }
        }
    }
    __syncthreads();
    // chunk 1: k rows 96..199 into local rows 0..103
    for (int i = tid; i < 104*104; i += 256) {
        int k = i / 104, n = i % 104;
        w3c[i] = (n < 100) ? to_tf32(g_w3[(96 + k)*100 + n]) : 0.f;
    }
    __syncthreads();
    #pragma unroll 1
    for (int kt = 12; kt < 25; kt++) {
        int ak = kt*8;
        int lk = ak - 96;
        uint32_t a0 = __float_as_uint(Arow[ g   *204 + ak + tg    ]);
        uint32_t a1 = __float_as_uint(Arow[(g+8)*204 + ak + tg    ]);
        uint32_t a2 = __float_as_uint(Arow[ g   *204 + ak + tg + 4]);
        uint32_t a3 = __float_as_uint(Arow[(g+8)*204 + ak + tg + 4]);
        #pragma unroll
        for (int j = 0; j < 4; j++) {
            int nt = ng*4 + j;
            if (nt < 13) {
                uint32_t b0 = __float_as_uint(w3c[(lk + tg    )*104 + nt*8 + g]);
                uint32_t b1 = __float_as_uint(w3c[(lk + tg + 4)*104 + nt*8 + g]);
                asm volatile(
                    "mma.sync.aligned.m16n8k8.row.col.f32.tf32.tf32.f32 "
                    "{%0,%1,%2,%3}, {%4,%5,%6,%7}, {%8,%9}, {%0,%1,%2,%3};"
                    : "+f"(acc[j][0]), "+f"(acc[j][1]), "+f"(acc[j][2]), "+f"(acc[j][3])
                    : "r"(a0), "r"(a1), "r"(a2), "r"(a3), "r"(b0), "r"(b1));
            }
        }
    }

    size_t row_lo = row0 + mt*16 + g;
    size_t row_hi = row_lo + 8;
    #pragma unroll
    for (int j = 0; j < 4; j++) {
        int nt = ng*4 + j;
        if (nt < 13) {
            int c = nt*8 + tg*2;
            if (c < 100) {
                g_hcomb[row_lo*Dn + c] = g_hlocal[row_lo*Dn + c] + fmaxf(acc[j][0], 0.f);
                g_hcomb[row_hi*Dn + c] = g_hlocal[row_hi*Dn + c] + fmaxf(acc[j][2], 0.f);
            }
            if (c + 1 < 100) {
                g_hcomb[row_lo*Dn + c + 1] = g_hlocal[row_lo*Dn + c + 1] + fmaxf(acc[j][1], 0.f);
                g_hcomb[row_hi*Dn + c + 1] = g_hlocal[row_hi*Dn + c + 1] + fmaxf(acc[j][3], 0.f);
            }
        }
    }
}

// ---------------- K5a: seq gather (parallel), hs, hsg ----------------
__global__ __launch_bounds__(256) void k_seqhs(
    const int* __restrict__ alias, const float* __restrict__ mask,
    const float* __restrict__ glu2_w, const float* __restrict__ glu2_b)
{
    int b = blockIdx.x, tid = threadIdx.x;
    __shared__ float seqs[Ldim][Dn];
    __shared__ float hs_s[Dn];
    __shared__ int alias_s[Ldim];
    __shared__ float mk_s[Ldim];
    if (tid < Ldim) { alias_s[tid] = alias[b*Ldim + tid]; mk_s[tid] = mask[b*Ldim + tid]; }
    __syncthreads();
    for (int idx = tid; idx < Ldim*Dn; idx += 256) {
        int l = idx / Dn, c = idx % Dn;
        float v = g_hcomb[((size_t)b*Ldim + alias_s[l])*Dn + c];
        seqs[l][c] = v;
        g_seq[((size_t)b*Ldim + l)*Dn + c] = v;
    }
    __syncthreads();
    if (tid < Dn) {
        float acc = 0.f, msum = 0.f;
        for (int l = 0; l < Ldim; l++) {
            acc = fmaf(seqs[l][tid], mk_s[l], acc);
            msum += mk_s[l];
        }
        hs_s[tid] = acc / msum;
    }
    __syncthreads();
    if (tid < Dn) {
        float t = glu2_b[tid];
        for (int c = 0; c < Dn; c++) t = fmaf(hs_s[c], __ldg(&glu2_w[c*Dn + tid]), t);
        g_hsg[b*Dn + tid] = t;
    }
}

// ---------------- K5b: fused nh + GLU + select (tf32 mma x2) ----------------
#define NS_WA   0        // 200*104 = 20800
#define NS_INS  20800    // 32*204  = 6528  -> 27328
#define NS_NH   27328    // 32*108  = 3456  -> 30784
#define NS_HB   30784    // 104
#define NS_W2   30888    // 104
#define NS_RED  30992    // 32*4 = 128
#define NS_BETA 31120    // 32
#define NS_TOT  31152
__global__ __launch_bounds__(256) void k_nhsel(
    const float* __restrict__ pos_emb, const float* __restrict__ w_1,
    const float* __restrict__ glu1_w, const float* __restrict__ glu1_b,
    const float* __restrict__ w_2, const float* __restrict__ mask)
{
    extern __shared__ float sm[];
    float* wA    = sm + NS_WA;
    float* ins   = sm + NS_INS;
    float* nh    = sm + NS_NH;
    float* hb_s  = sm + NS_HB;
    float* w2s   = sm + NS_W2;
    float* red   = sm + NS_RED;
    float* beta_s= sm + NS_BETA;
    int tid = threadIdx.x;
    int lane = tid & 31, warp = tid >> 5;
    int row0 = blockIdx.x * 32;
    int b = row0 >> 6;
    int lbase = row0 & 63;

    for (int i = tid; i < 200*104; i += 256) wA[i] = 0.f;
    if (tid < 104) {
        hb_s[tid] = (tid < Dn) ? glu1_b[tid] + g_hsg[b*Dn + tid] : 0.f;
        w2s[tid]  = (tid < Dn) ? w_2[tid] : 0.f;
    }
    __syncthreads();
    for (int i = tid; i < 200*100; i += 256) {
        int k = i / 100, n = i % 100;
        wA[k*104 + n] = to_tf32(w_1[i]);
    }
    for (int idx = tid; idx < 32*25; idx += 256) {
        int r = idx / 25, c4 = (idx % 25) * 4;
        size_t row = row0 + r;
        int l = (int)(row % Ldim);
        float4 vp = *(const float4*)(pos_emb + l*Dn + c4);
        float4 vs = *(const float4*)(g_seq + row*Dn + c4);
        float* d = ins + r*204;
        d[c4+0] = to_tf32(vp.x); d[c4+1] = to_tf32(vp.y);
        d[c4+2] = to_tf32(vp.z); d[c4+3] = to_tf32(vp.w);
        d[100+c4+0] = to_tf32(vs.x); d[100+c4+1] = to_tf32(vs.y);
        d[100+c4+2] = to_tf32(vs.z); d[100+c4+3] = to_tf32(vs.w);
    }
    if (tid < 32) {
        float* d = ins + tid*204 + 200;
        d[0] = 0.f; d[1] = 0.f; d[2] = 0.f; d[3] = 0.f;
        float* d2 = nh + tid*108 + 100;
        #pragma unroll
        for (int q = 0; q < 8; q++) d2[q] = 0.f;
    }
    __syncthreads();

    int g = lane >> 2, tg = lane & 3;
    int mt = warp & 1;
    int ng = warp >> 1;
    int rl = mt*16 + g, rh = rl + 8;

    // GEMM1: [32 x 200] @ w_1 -> tanh -> nh
    {
        float acc[4][4];
        #pragma unroll
        for (int j = 0; j < 4; j++)
            #pragma unroll
            for (int q = 0; q < 4; q++) acc[j][q] = 0.f;
        const float* Arow = ins + mt*16*204;
        #pragma unroll 1
        for (int kt = 0; kt < 25; kt++) {
            int ak = kt*8;
            uint32_t a0 = __float_as_uint(Arow[ g   *204 + ak + tg    ]);
            uint32_t a1 = __float_as_uint(Arow[(g+8)*204 + ak + tg    ]);
            uint32_t a2 = __float_as_uint(Arow[ g   *204 + ak + tg + 4]);
            uint32_t a3 = __float_as_uint(Arow[(g+8)*204 + ak + tg + 4]);
            #pragma unroll
            for (int j = 0; j < 4; j++) {
                int nt = ng*4 + j;
                if (nt < 13) {
                    uint32_t b0 = __float_as_uint(wA[(ak + tg    )*104 + nt*8 + g]);
                    uint32_t b1 = __float_as_uint(wA[(ak + tg + 4)*104 + nt*8 + g]);
                    asm volatile(
                        "mma.sync.aligned.m16n8k8.row.col.f32.tf32.tf32.f32 "
                        "{%0,%1,%2,%3}, {%4,%5,%6,%7}, {%8,%9}, {%0,%1,%2,%3};"
                        : "+f"(acc[j][0]), "+f"(acc[j][1]), "+f"(acc[j][2]), "+f"(acc[j][3])
                        : "r"(a0), "r"(a1), "r"(a2), "r"(a3), "r"(b0), "r"(b1));
                }
            }
        }
        #pragma unroll
        for (int j = 0; j < 4; j++) {
            int nt = ng*4 + j;
            if (nt < 13) {
                int c = nt*8 + tg*2;
                if (c < 100) {
                    nh[rl*108 + c] = to_tf32(tanhf(acc[j][0]));
                    nh[rh*108 + c] = to_tf32(tanhf(acc[j][2]));
                }
                if (c + 1 < 100) {
                    nh[rl*108 + c + 1] = to_tf32(tanhf(acc[j][1]));
                    nh[rh*108 + c + 1] = to_tf32(tanhf(acc[j][3]));
                }
            }
        }
    }
    __syncthreads();
    for (int i = tid; i < 104*104; i += 256) wA[i] = 0.f;
    __syncthreads();
    for (int i = tid; i < 100*100; i += 256) {
        int k = i / 100, n = i % 100;
        wA[k*104 + n] = to_tf32(glu1_w[i]);
    }
    __syncthreads();

    // GEMM2: t = nh @ glu1_w; sigmoid(t + hb); beta partials
    {
        float t[4][4];
        #pragma unroll
        for (int j = 0; j < 4; j++)
            #pragma unroll
            for (int q = 0; q < 4; q++) t[j][q] = 0.f;
        const float* A2 = nh + mt*16*108;
        #pragma unroll 1
        for (int kt = 0; kt < 13; kt++) {
            int ak = kt*8;
            uint32_t a0 = __float_as_uint(A2[ g   *108 + ak + tg    ]);
            uint32_t a1 = __float_as_uint(A2[(g+8)*108 + ak + tg    ]);
            uint32_t a2 = __float_as_uint(A2[ g   *108 + ak + tg + 4]);
            uint32_t a3 = __float_as_uint(A2[(g+8)*108 + ak + tg + 4]);
            #pragma unroll
            for (int j = 0; j < 4; j++) {
                int nt = ng*4 + j;
                if (nt < 13) {
                    uint32_t b0 = __float_as_uint(wA[(ak + tg    )*104 + nt*8 + g]);
                    uint32_t b1 = __float_as_uint(wA[(ak + tg + 4)*104 + nt*8 + g]);
                    asm volatile(
                        "mma.sync.aligned.m16n8k8.row.col.f32.tf32.tf32.f32 "
                        "{%0,%1,%2,%3}, {%4,%5,%6,%7}, {%8,%9}, {%0,%1,%2,%3};"
                        : "+f"(t[j][0]), "+f"(t[j][1]), "+f"(t[j][2]), "+f"(t[j][3])
                        : "r"(a0), "r"(a1), "r"(a2), "r"(a3), "r"(b0), "r"(b1));
                }
            }
        }
        float p_lo = 0.f, p_hi = 0.f;
        #pragma unroll
        for (int j = 0; j < 4; j++) {
            int nt = ng*4 + j;
            if (nt < 13) {
                int c = nt*8 + tg*2;
                if (c < 100) {
                    float s0 = 1.f / (1.f + __expf(-(t[j][0] + hb_s[c])));
                    float s2 = 1.f / (1.f + __expf(-(t[j][2] + hb_s[c])));
                    p_lo = fmaf(s0, w2s[c], p_lo);
                    p_hi = fmaf(s2, w2s[c], p_hi);
                }
                if (c + 1 < 100) {
                    float s1 = 1.f / (1.f + __expf(-(t[j][1] + hb_s[c+1])));
                    float s3 = 1.f / (1.f + __expf(-(t[j][3] + hb_s[c+1])));
                    p_lo = fmaf(s1, w2s[c+1], p_lo);
                    p_hi = fmaf(s3, w2s[c+1], p_hi);
                }
            }
        }
        p_lo += __shfl_xor_sync(0xffffffffu, p_lo, 1);
        p_lo += __shfl_xor_sync(0xffffffffu, p_lo, 2);
        p_hi += __shfl_xor_sync(0xffffffffu, p_hi, 1);
        p_hi += __shfl_xor_sync(0xffffffffu, p_hi, 2);
        if (tg == 0) {
            red[rl*4 + ng] = p_lo;
            red[rh*4 + ng] = p_hi;
        }
    }
    __syncthreads();
    if (tid < 32) {
        float s = red[tid*4] + red[tid*4+1] + red[tid*4+2] + red[tid*4+3];
        beta_s[tid] = s * mask[b*Ldim + lbase + tid];
    }
    __syncthreads();

    if (tid < Dn) {
        float sel = 0.f;
        #pragma unroll 8
        for (int r = 0; r < 32; r++)
            sel = fmaf(beta_s[r], ins[r*204 + 100 + tid], sel);
        g_selpart[blockIdx.x*Dn + tid] = sel;
    }
}

// ---------------- K6a: score (tf32 mma, 64-row batch tile) ------------------
#define SC_EMB  6656          // after sel_s 64*104
#define SC_TOT  (6656 + 128*104)   // 19968 floats
__global__ __launch_bounds__(256) void k_score(
    const float* __restrict__ emb, float* __restrict__ out)
{
    extern __shared__ float sm[];
    float* sel_s = sm;
    float* emb_s = sm + SC_EMB;
    int n0 = blockIdx.x * 128, b0 = blockIdx.y * 64;
    int tid = threadIdx.x;
    int lane = tid & 31, warp = tid >> 5;

    for (int idx = tid; idx < 64*25; idx += 256) {
        int r = idx / 25, c4 = (idx % 25) * 4;
        int bb = b0 + r;
        float4 v0 = *(const float4*)(g_selpart + (2*bb)*Dn + c4);
        float4 v1 = *(const float4*)(g_selpart + (2*bb+1)*Dn + c4);
        float* d = sel_s + r*104 + c4;
        d[0] = to_tf32(v0.x + v1.x); d[1] = to_tf32(v0.y + v1.y);
        d[2] = to_tf32(v0.z + v1.z); d[3] = to_tf32(v0.w + v1.w);
    }
    if (tid < 64) {
        float* d = sel_s + tid*104 + 100;
        d[0] = 0.f; d[1] = 0.f; d[2] = 0.f; d[3] = 0.f;
    }
    for (int idx = tid; idx < 128*25; idx += 256) {
        int r = idx / 25, c4 = (idx % 25) * 4;
        int n = n0 + r;
        float4 v = make_float4(0.f,0.f,0.f,0.f);
        if (n < NOUT) v = *(const float4*)(emb + (size_t)(n + 1)*Dn + c4);
        float* d = emb_s + r*104 + c4;
        d[0] = to_tf32(v.x); d[1] = to_tf32(v.y);
        d[2] = to_tf32(v.z); d[3] = to_tf32(v.w);
    }
    if (tid < 128) {
        float* d = emb_s + tid*104 + 100;
        d[0] = 0.f; d[1] = 0.f; d[2] = 0.f; d[3] = 0.f;
    }
    __syncthreads();

    int g = lane >> 2, tg = lane & 3;
    int mt = warp & 3;            // 4 m-tiles of 16 rows
    int nb = warp >> 2;           // 2 n-groups of 8 n-tiles
    const float* Arow = sel_s + mt*16*104;

    float acc[8][4];
    #pragma unroll
    for (int j = 0; j < 8; j++)
        #pragma unroll
        for (int q = 0; q < 4; q++) acc[j][q] = 0.f;

    #pragma unroll 1
    for (int kt = 0; kt < 13; kt++) {
        int ak = kt*8;
        uint32_t a0 = __float_as_uint(Arow[ g   *104 + ak + tg    ]);
        uint32_t a1 = __float_as_uint(Arow[(g+8)*104 + ak + tg    ]);
        uint32_t a2 = __float_as_uint(Arow[ g   *104 + ak + tg + 4]);
        uint32_t a3 = __float_as_uint(Arow[(g+8)*104 + ak + tg + 4]);
        #pragma unroll
        for (int j = 0; j < 8; j++) {
            int nt = nb*8 + j;
            uint32_t bb0 = __float_as_uint(emb_s[(nt*8 + g)*104 + ak + tg    ]);
            uint32_t bb1 = __float_as_uint(emb_s[(nt*8 + g)*104 + ak + tg + 4]);
            asm volatile(
                "mma.sync.aligned.m16n8k8.row.col.f32.tf32.tf32.f32 "
                "{%0,%1,%2,%3}, {%4,%5,%6,%7}, {%8,%9}, {%0,%1,%2,%3};"
                : "+f"(acc[j][0]), "+f"(acc[j][1]), "+f"(acc[j][2]), "+f"(acc[j][3])
                : "r"(a0), "r"(a1), "r"(a2), "r"(a3), "r"(bb0), "r"(bb1));
        }
    }

    int row_lo = b0 + mt*16 + g;
    int row_hi = row_lo + 8;
    float rmax_lo = -3.0e38f, rmax_hi = -3.0e38f;
    #pragma unroll
    for (int j = 0; j < 8; j++) {
        int nt = nb*8 + j;
        int ncol = n0 + nt*8 + tg*2;
        if (ncol < NOUT) {
            out[(size_t)row_lo*NOUT + ncol] = acc[j][0];
            out[(size_t)row_hi*NOUT + ncol] = acc[j][2];
            rmax_lo = fmaxf(rmax_lo, acc[j][0]);
            rmax_hi = fmaxf(rmax_hi, acc[j][2]);
        }
        if (ncol + 1 < NOUT) {
            out[(size_t)row_lo*NOUT + ncol + 1] = acc[j][1];
            out[(size_t)row_hi*NOUT + ncol + 1] = acc[j][3];
            rmax_lo = fmaxf(rmax_lo, acc[j][1]);
            rmax_hi = fmaxf(rmax_hi, acc[j][3]);
        }
    }
    rmax_lo = fmaxf(rmax_lo, __shfl_xor_sync(0xffffffffu, rmax_lo, 1));
    rmax_lo = fmaxf(rmax_lo, __shfl_xor_sync(0xffffffffu, rmax_lo, 2));
    rmax_hi = fmaxf(rmax_hi, __shfl_xor_sync(0xffffffffu, rmax_hi, 1));
    rmax_hi = fmaxf(rmax_hi, __shfl_xor_sync(0xffffffffu, rmax_hi, 2));
    if (tg == 0) {
        atomicMax(&g_rmaxbits[row_lo], fkey(rmax_lo));
        atomicMax(&g_rmaxbits[row_hi], fkey(rmax_hi));
    }
}

// ---------------- K6b: per-chunk sum of exp ----------------
__global__ __launch_bounds__(256) void k_expsum(const float* __restrict__ out)
{
    int b = blockIdx.y, chunk = blockIdx.x, tid = threadIdx.x;
    int start = chunk * CHUNKSZ;
    int end = start + CHUNKSZ; if (end > NOUT) end = NOUT;
    float m = funkey(g_rmaxbits[b]);
    float s = 0.f;
    for (int n = start + tid; n < end; n += 256)
        s += fexp(out[(size_t)b*NOUT + n] - m);
    __shared__ float red[256];
    red[tid] = s;
    __syncthreads();
    for (int st = 128; st > 0; st >>= 1) {
        if (tid < st) red[tid] += red[tid + st];
        __syncthreads();
    }
    if (tid == 0) g_rpart[b*NCHUNK + chunk] = red[0];
}

// ---------------- K6c: exp + scale ----------------
__global__ __launch_bounds__(256) void k_scale(float* __restrict__ out)
{
    int b = blockIdx.y;
    int n = blockIdx.x * 256 + threadIdx.x;
    if (n < NOUT) {
        float ssum = 0.f;
        #pragma unroll
        for (int j = 0; j < NCHUNK; j++) ssum += g_rpart[b*NCHUNK + j];
        float m = funkey(g_rmaxbits[b]);
        float inv = __fdividef(1.f, ssum);
        size_t idx = (size_t)b*NOUT + n;
        out[idx] = fexp(out[idx] - m) * inv;
    }
}

// ---------------- launch ----------------
extern "C" void kernel_launch(void* const* d_in, const int* in_sizes, int n_in,
                              void* d_out, int out_size)
{
    const int*   alias_inputs = (const int*)  d_in[0];
    const int*   items        = (const int*)  d_in[1];
    const int*   adj          = (const int*)  d_in[2];
    const float* mask_item    = (const float*)d_in[3];
    const int*   seq_features = (const int*)  d_in[4];
    const int*   adj_all      = (const int*)  d_in[5];
    const float* num_w        = (const float*)d_in[6];
    const float* emb          = (const float*)d_in[7];
    const float* pos_emb      = (const float*)d_in[8];
    const float* a0           = (const float*)d_in[9];
    const float* a1           = (const float*)d_in[10];
    const float* a2           = (const float*)d_in[11];
    const float* a3           = (const float*)d_in[12];
    const float* g_w1         = (const float*)d_in[13];
    const float* g_w2         = (const float*)d_in[14];
    const float* g_w3         = (const float*)d_in[15];
    const float* w_1          = (const float*)d_in[16];
    const float* w_2          = (const float*)d_in[17];
    const float* glu1_w       = (const float*)d_in[18];
    const float* glu1_b       = (const float*)d_in[19];
    const float* glu2_w       = (const float*)d_in[20];
    const float* glu2_b       = (const float*)d_in[21];
    float* out = (float*)d_out;

    static cudaStream_t s2 = nullptr;
    static cudaEvent_t ev_fork = nullptr, ev_join = nullptr;
    static bool attr_done = false;
    if (!s2) {
        cudaStreamCreateWithFlags(&s2, cudaStreamNonBlocking);
        cudaEventCreateWithFlags(&ev_fork, cudaEventDisableTiming);
        cudaEventCreateWithFlags(&ev_join, cudaEventDisableTiming);
    }

    const int GSMEM = GT_TOT * 4;                  // ~86.3 KB
    const int CSMEM = CB_TOT * 4;                  // ~69.4 KB
    const int NSMEM = NS_TOT * 4;                  // ~124.6 KB
    const int SSMEM = SC_TOT * 4;                  // ~79.9 KB
    if (!attr_done) {
        cudaFuncSetAttribute(k_global,  cudaFuncAttributeMaxDynamicSharedMemorySize, GSMEM);
        cudaFuncSetAttribute(k_combine, cudaFuncAttributeMaxDynamicSharedMemorySize, CSMEM);
        cudaFuncSetAttribute(k_nhsel,   cudaFuncAttributeMaxDynamicSharedMemorySize, NSMEM);
        cudaFuncSetAttribute(k_score,   cudaFuncAttributeMaxDynamicSharedMemorySize, SSMEM);
        attr_done = true;
    }

    k_init   <<<1, 256>>>();
    cudaEventRecord(ev_fork, 0);
    cudaStreamWaitEvent(s2, ev_fork, 0);
    k_local  <<<Bn*2, 256, 0, s2>>>(items, adj, emb, a0, a1, a2, a3);
    k_global <<<Bn*2, 256, GSMEM>>>(items, adj_all, num_w, emb, g_w1, g_w2,
                                    seq_features, mask_item);
    cudaEventRecord(ev_join, s2);
    cudaStreamWaitEvent(0, ev_join, 0);
    k_combine<<<(Bn*Ldim)/32, 256, CSMEM>>>(g_w3);
    k_seqhs  <<<Bn, 256>>>(alias_inputs, mask_item, glu2_w, glu2_b);
    k_nhsel  <<<(Bn*Ldim)/32, 256, NSMEM>>>(pos_emb, w_1, glu1_w, glu1_b, w_2, mask_item);
    dim3 gs((NOUT + 127)/128, Bn/64);
    k_score  <<<gs, 256, SSMEM>>>(emb, out);
    dim3 ge(NCHUNK, Bn);
    k_expsum <<<ge, 256>>>(out);
    dim3 gn((NOUT + 255)/256, Bn);
    k_scale  <<<gn, 256>>>(out);
}

// round 16
// speedup vs baseline: 1.0208x; 1.0208x over previous
#include <cuda_runtime.h>
#include <math.h>
#include <stdint.h>

#define Bn 256
#define Ldim 64
#define Sn 12
#define Dn 100
#define NUM_NODE 43098
#define NOUT 43097
#define NEGV -9000000000000000.0f
#define NCHUNK 8
#define CHUNKSZ 5388   // ceil(43097/8)

// ---------------- scratch (device globals; no allocation) ----------------
__device__ float g_h[Bn*Ldim*Dn];
__device__ float g_hlocal[Bn*Ldim*Dn];
__device__ float g_nb[Bn*Ldim*Dn];
__device__ float g_hcomb[Bn*Ldim*Dn];
__device__ float g_seq[Bn*Ldim*Dn];
__device__ float g_hsg[Bn*Dn];
__device__ float g_selpart[2*Bn*Dn];
__device__ unsigned g_rmaxbits[Bn];
__device__ float g_rpart[Bn*NCHUNK];

__device__ __forceinline__ unsigned fkey(float f) {
    unsigned u = __float_as_uint(f);
    return (u & 0x80000000u) ? ~u : (u | 0x80000000u);
}
__device__ __forceinline__ float funkey(unsigned k) {
    return (k & 0x80000000u) ? __uint_as_float(k ^ 0x80000000u)
                             : __uint_as_float(~k);
}

__device__ __forceinline__ float fexp(float x) {
    float y = x * 1.44269504088896340736f;
    y = fmaxf(y, -126.0f);
    float t = y + 12582912.0f;
    float i = t - 12582912.0f;
    float f = y - i;
    int ii = (int)i;
    float p = 1.54035303933816e-4f;
    p = fmaf(p, f, 1.33335581464284e-3f);
    p = fmaf(p, f, 9.61812910762848e-3f);
    p = fmaf(p, f, 5.55041086648216e-2f);
    p = fmaf(p, f, 2.40226506959101e-1f);
    p = fmaf(p, f, 6.93147180559945e-1f);
    p = fmaf(p, f, 1.0f);
    return p * __int_as_float((ii + 127) << 23);
}

__device__ __forceinline__ float to_tf32(float x) {
    uint32_t r;
    asm("cvt.rna.tf32.f32 %0, %1;" : "=r"(r) : "f"(x));
    return __uint_as_float(r);
}

// ---------------- K0 ----------------
__global__ void k_init() {
    int t = threadIdx.x;
    if (t < Bn) g_rmaxbits[t] = 0u;
}

// ---------------- K1: local graph attention (float4, 2 CTAs/row) -----------
__global__ __launch_bounds__(256) void k_local(
    const int* __restrict__ items, const int* __restrict__ adj,
    const float* __restrict__ emb,
    const float* __restrict__ a0, const float* __restrict__ a1,
    const float* __restrict__ a2, const float* __restrict__ a3)
{
    int b = blockIdx.x >> 1;
    int half = blockIdx.x & 1;
    int i0 = half * 32;
    __shared__ float hs[Ldim][108];
    __shared__ float alpha[32][Ldim+1];
    __shared__ float At[4][108];
    int tid = threadIdx.x;

    for (int i = tid; i < Dn; i += 256) {
        At[0][i] = a0[i]; At[1][i] = a1[i]; At[2][i] = a2[i]; At[3][i] = a3[i];
    }
    for (int idx = tid; idx < Ldim*25; idx += 256) {
        int l = idx / 25, c4 = (idx % 25) * 4;
        float4 v = *(const float4*)(emb + (size_t)items[b*Ldim + l]*Dn + c4);
        *(float4*)(&hs[l][c4]) = v;
    }
    __syncthreads();
    for (int idx = tid; idx < 32*25; idx += 256) {
        int l = i0 + idx / 25, c4 = (idx % 25) * 4;
        *(float4*)(g_h + ((size_t)b*Ldim + l)*Dn + c4) = *(const float4*)(&hs[l][c4]);
    }

    for (int p = tid; p < 32*Ldim; p += 256) {
        int il = p >> 6, j = p & 63;
        int i = i0 + il;
        int a = adj[((size_t)b*Ldim + i)*Ldim + j];
        float val = NEGV;
        if (a >= 1 && a <= 4) {
            int k = a - 1;
            const float4* hi = (const float4*)hs[i];
            const float4* hj = (const float4*)hs[j];
            const float4* at = (const float4*)At[k];
            float acc = 0.f;
            #pragma unroll 5
            for (int d4 = 0; d4 < 25; d4++) {
                float4 x = hi[d4], y = hj[d4], w = at[d4];
                acc = fmaf(x.x*y.x, w.x, acc);
                acc = fmaf(x.y*y.y, w.y, acc);
                acc = fmaf(x.z*y.z, w.z, acc);
                acc = fmaf(x.w*y.w, w.w, acc);
            }
            val = acc > 0.f ? acc : 0.2f * acc;
        }
        alpha[il][j] = val;
    }
    __syncthreads();

    int warp = tid >> 5, lane = tid & 31;
    for (int il = warp; il < 32; il += 8) {
        float x0 = alpha[il][lane], x1 = alpha[il][lane+32];
        float m = fmaxf(x0, x1);
        #pragma unroll
        for (int o = 16; o > 0; o >>= 1) m = fmaxf(m, __shfl_xor_sync(0xffffffffu, m, o));
        float e0 = __expf(fmaxf(x0 - m, -87.f));
        float e1 = __expf(fmaxf(x1 - m, -87.f));
        float s = e0 + e1;
        #pragma unroll
        for (int o = 16; o > 0; o >>= 1) s += __shfl_xor_sync(0xffffffffu, s, o);
        float inv = 1.f / s;
        alpha[il][lane] = e0 * inv;
        alpha[il][lane+32] = e1 * inv;
    }
    __syncthreads();

    for (int idx = tid; idx < 32*25; idx += 256) {
        int il = idx / 25, c4 = (idx % 25) * 4;
        float ax = 0.f, ay = 0.f, az = 0.f, aw = 0.f;
        for (int j = 0; j < Ldim; j++) {
            float al = alpha[il][j];
            float4 v = *(const float4*)(&hs[j][c4]);
            ax = fmaf(al, v.x, ax);
            ay = fmaf(al, v.y, ay);
            az = fmaf(al, v.z, az);
            aw = fmaf(al, v.w, aw);
        }
        *(float4*)(g_hlocal + ((size_t)b*Ldim + i0 + il)*Dn + c4)
            = make_float4(ax, ay, az, aw);
    }
}

// ---------------- K3: global neighbor aggregation (tf32 mma; in-CTA sess) --
#define GT_W1   0        // 104*104 = 10816
#define GT_FEAT 10816    // 96*108  = 10368
#define GT_W2   21184    // 104
#define GT_SESS 21288    // 100
#define GT_ALSC 21388    // 96
#define GT_NBR  21484    // 96 ints
#define GT_TOT  21580
__global__ __launch_bounds__(256, 2) void k_global(
    const int* __restrict__ items, const int* __restrict__ adj_all,
    const float* __restrict__ num_w, const float* __restrict__ emb,
    const float* __restrict__ g_w1, const float* __restrict__ g_w2,
    const int* __restrict__ seq_features, const float* __restrict__ mask)
{
    extern __shared__ float sm[];
    float* w1s   = sm + GT_W1;
    float* feat  = sm + GT_FEAT;
    float* w2s   = sm + GT_W2;
    float* sesss = sm + GT_SESS;
    float* alsc  = sm + GT_ALSC;
    int*   nbrs  = (int*)(sm + GT_NBR);

    int blk = blockIdx.x;
    int b = blk >> 1;
    int l0 = (blk & 1) * 32;
    int tid = threadIdx.x;
    int lane = tid & 31, warp = tid >> 5;

    for (int i = tid; i < 104*104; i += 256) w1s[i] = 0.f;
    if (tid < 104) w2s[tid] = (tid < Dn) ? g_w2[tid] : 0.f;
    if (tid < Ldim) alsc[tid] = mask[b*Ldim + tid];
    for (int idx = tid; idx < Ldim*25; idx += 256) {
        int r = idx / 25, c4 = (idx % 25) * 4;
        float4 v = *(const float4*)(emb + (size_t)seq_features[b*Ldim + r]*Dn + c4);
        *(float4*)(feat + r*108 + c4) = v;
    }
    __syncthreads();
    if (tid < Dn) {
        float s = 0.f, ms = 0.f;
        for (int l = 0; l < Ldim; l++) {
            s = fmaf(feat[l*108 + tid], alsc[l], s);
            ms += alsc[l];
        }
        sesss[tid] = s / ms;
    }
    __syncthreads();
    for (int i = tid; i < 101*100; i += 256) {
        int k = i / 100, n = i % 100;
        float scale = (k < 100) ? sesss[k] : 1.f;
        w1s[k*104 + n] = to_tf32(g_w1[i] * scale);
    }
    __syncthreads();

    int g = lane >> 2, tg = lane & 3;

    for (int it = 0; it < 4; it++) {
        int lbase = l0 + it*8;
        if (tid < 96) {
            int l = tid / 12, s = tid % 12;
            int node = items[b*Ldim + lbase + l];
            nbrs[tid] = adj_all[(size_t)node*Sn + s];
            feat[tid*108 + 100] = to_tf32(num_w[(size_t)node*Sn + s]);
            feat[tid*108 + 101] = 0.f;
            feat[tid*108 + 102] = 0.f;
            feat[tid*108 + 103] = 0.f;
        }
        for (int idx = tid; idx < 96*25; idx += 256) {
            int r = idx / 25, c4 = (idx % 25) * 4;
            int node = items[b*Ldim + lbase + r/12];
            int nbr  = adj_all[(size_t)node*Sn + (r%12)];
            float4 e = *(const float4*)(emb + (size_t)nbr*Dn + c4);
            float* dst = feat + r*108 + c4;
            dst[0] = to_tf32(e.x);
            dst[1] = to_tf32(e.y);
            dst[2] = to_tf32(e.z);
            dst[3] = to_tf32(e.w);
        }
        __syncthreads();

        if (warp < 6) {
            const float* Ab = feat + warp*16*108;
            float acc[13][4];
            #pragma unroll
            for (int nt = 0; nt < 13; nt++)
                #pragma unroll
                for (int q = 0; q < 4; q++) acc[nt][q] = 0.f;

            #pragma unroll 1
            for (int kt = 0; kt < 13; kt++) {
                int ak = kt*8;
                uint32_t a0 = __float_as_uint(Ab[ g   *108 + ak + tg    ]);
                uint32_t a1 = __float_as_uint(Ab[(g+8)*108 + ak + tg    ]);
                uint32_t a2 = __float_as_uint(Ab[ g   *108 + ak + tg + 4]);
                uint32_t a3 = __float_as_uint(Ab[(g+8)*108 + ak + tg + 4]);
                const float* wrow0 = w1s + (ak + tg)*104;
                const float* wrow1 = w1s + (ak + tg + 4)*104;
                #pragma unroll
                for (int nt = 0; nt < 13; nt++) {
                    uint32_t b0 = __float_as_uint(wrow0[nt*8 + g]);
                    uint32_t b1 = __float_as_uint(wrow1[nt*8 + g]);
                    asm volatile(
                        "mma.sync.aligned.m16n8k8.row.col.f32.tf32.tf32.f32 "
                        "{%0,%1,%2,%3}, {%4,%5,%6,%7}, {%8,%9}, {%0,%1,%2,%3};"
                        : "+f"(acc[nt][0]), "+f"(acc[nt][1]), "+f"(acc[nt][2]), "+f"(acc[nt][3])
                        : "r"(a0), "r"(a1), "r"(a2), "r"(a3), "r"(b0), "r"(b1));
                }
            }

            float score_a = 0.f, score_b = 0.f;
            #pragma unroll
            for (int nt = 0; nt < 13; nt++) {
                int j0 = nt*8 + tg*2;
                float w20 = w2s[j0], w21 = w2s[j0+1];
                float v0 = acc[nt][0] > 0.f ? acc[nt][0] : 0.2f*acc[nt][0];
                float v1 = acc[nt][1] > 0.f ? acc[nt][1] : 0.2f*acc[nt][1];
                float v2 = acc[nt][2] > 0.f ? acc[nt][2] : 0.2f*acc[nt][2];
                float v3 = acc[nt][3] > 0.f ? acc[nt][3] : 0.2f*acc[nt][3];
                score_a = fmaf(v0, w20, fmaf(v1, w21, score_a));
                score_b = fmaf(v2, w20, fmaf(v3, w21, score_b));
            }
            score_a += __shfl_xor_sync(0xffffffffu, score_a, 1);
            score_a += __shfl_xor_sync(0xffffffffu, score_a, 2);
            score_b += __shfl_xor_sync(0xffffffffu, score_b, 1);
            score_b += __shfl_xor_sync(0xffffffffu, score_b, 2);
            if (tg == 0) {
                alsc[warp*16 + g]     = score_a;
                alsc[warp*16 + g + 8] = score_b;
            }
        }
        __syncthreads();

        if (tid < 8) {
            float* a = alsc + tid*12;
            float m = a[0];
            #pragma unroll
            for (int s = 1; s < Sn; s++) m = fmaxf(m, a[s]);
            float ssum = 0.f;
            float e[Sn];
            #pragma unroll
            for (int s = 0; s < Sn; s++) { e[s] = __expf(a[s] - m); ssum += e[s]; }
            float inv = 1.f / ssum;
            #pragma unroll
            for (int s = 0; s < Sn; s++) a[s] = e[s] * inv;
        }
        __syncthreads();

        for (int idx = tid; idx < 800; idx += 256) {
            int l = idx / 100, c = idx % 100;
            const float* fr = feat + (l*12)*108 + c;
            const float* al = alsc + l*12;
            float acc2 = 0.f;
            #pragma unroll
            for (int s = 0; s < Sn; s++)
                acc2 = fmaf(al[s], fr[s*108], acc2);
            g_nb[((size_t)b*Ldim + lbase + l)*Dn + c] = acc2;
        }
        __syncthreads();
    }
}

// ---------------- K4: h_combine = relu([h,nb]@g_w3) + h_local (tf32 mma) ----
// R13 version: monolithic w3s, grid 256, 2 row-iterations per CTA
#define CB_W3  0             // 200*104 = 20800
#define CB_INS 20800         // 32*204  = 6528
#define CB_TOT 27328
__global__ __launch_bounds__(256) void k_combine(const float* __restrict__ g_w3)
{
    extern __shared__ float sm[];
    float* w3s = sm + CB_W3;
    float* ins = sm + CB_INS;
    int tid = threadIdx.x;
    int lane = tid & 31, warp = tid >> 5;

    for (int i = tid; i < 200*104; i += 256) w3s[i] = 0.f;
    __syncthreads();
    for (int i = tid; i < 200*100; i += 256) {
        int k = i / 100, n = i % 100;
        w3s[k*104 + n] = to_tf32(g_w3[i]);
    }
    __syncthreads();

    int g = lane >> 2, tg = lane & 3;
    int mt = warp & 1;
    int ng = warp >> 1;

    for (int it = 0; it < 2; it++) {
        int row0 = blockIdx.x * 64 + it * 32;
        for (int idx = tid; idx < 32*25; idx += 256) {
            int r = idx / 25, c4 = (idx % 25) * 4;
            size_t row = row0 + r;
            float4 vh = *(const float4*)(g_h  + row*Dn + c4);
            float4 vn = *(const float4*)(g_nb + row*Dn + c4);
            float* d = ins + r*204;
            d[c4+0]   = to_tf32(vh.x); d[c4+1]   = to_tf32(vh.y);
            d[c4+2]   = to_tf32(vh.z); d[c4+3]   = to_tf32(vh.w);
            d[100+c4+0] = to_tf32(vn.x); d[100+c4+1] = to_tf32(vn.y);
            d[100+c4+2] = to_tf32(vn.z); d[100+c4+3] = to_tf32(vn.w);
        }
        if (tid < 32) {
            float* d = ins + tid*204 + 200;
            d[0] = 0.f; d[1] = 0.f; d[2] = 0.f; d[3] = 0.f;
        }
        __syncthreads();

        float acc[4][4];
        #pragma unroll
        for (int j = 0; j < 4; j++)
            #pragma unroll
            for (int q = 0; q < 4; q++) acc[j][q] = 0.f;

        const float* Arow = ins + mt*16*204;
        #pragma unroll 1
        for (int kt = 0; kt < 25; kt++) {
            int ak = kt*8;
            uint32_t a0 = __float_as_uint(Arow[ g   *204 + ak + tg    ]);
            uint32_t a1 = __float_as_uint(Arow[(g+8)*204 + ak + tg    ]);
            uint32_t a2 = __float_as_uint(Arow[ g   *204 + ak + tg + 4]);
            uint32_t a3 = __float_as_uint(Arow[(g+8)*204 + ak + tg + 4]);
            #pragma unroll
            for (int j = 0; j < 4; j++) {
                int nt = ng*4 + j;
                if (nt < 13) {
                    uint32_t b0 = __float_as_uint(w3s[(ak + tg    )*104 + nt*8 + g]);
                    uint32_t b1 = __float_as_uint(w3s[(ak + tg + 4)*104 + nt*8 + g]);
                    asm volatile(
                        "mma.sync.aligned.m16n8k8.row.col.f32.tf32.tf32.f32 "
                        "{%0,%1,%2,%3}, {%4,%5,%6,%7}, {%8,%9}, {%0,%1,%2,%3};"
                        : "+f"(acc[j][0]), "+f"(acc[j][1]), "+f"(acc[j][2]), "+f"(acc[j][3])
                        : "r"(a0), "r"(a1), "r"(a2), "r"(a3), "r"(b0), "r"(b1));
                }
            }
        }

        size_t row_lo = row0 + mt*16 + g;
        size_t row_hi = row_lo + 8;
        #pragma unroll
        for (int j = 0; j < 4; j++) {
            int nt = ng*4 + j;
            if (nt < 13) {
                int c = nt*8 + tg*2;
                if (c < 100) {
                    g_hcomb[row_lo*Dn + c] = g_hlocal[row_lo*Dn + c] + fmaxf(acc[j][0], 0.f);
                    g_hcomb[row_hi*Dn + c] = g_hlocal[row_hi*Dn + c] + fmaxf(acc[j][2], 0.f);
                }
                if (c + 1 < 100) {
                    g_hcomb[row_lo*Dn + c + 1] = g_hlocal[row_lo*Dn + c + 1] + fmaxf(acc[j][1], 0.f);
                    g_hcomb[row_hi*Dn + c + 1] = g_hlocal[row_hi*Dn + c + 1] + fmaxf(acc[j][3], 0.f);
                }
            }
        }
        __syncthreads();
    }
}

// ---------------- K5a: seq gather (parallel), hs, hsg ----------------
__global__ __launch_bounds__(256) void k_seqhs(
    const int* __restrict__ alias, const float* __restrict__ mask,
    const float* __restrict__ glu2_w, const float* __restrict__ glu2_b)
{
    int b = blockIdx.x, tid = threadIdx.x;
    __shared__ float seqs[Ldim][Dn];
    __shared__ float hs_s[Dn];
    __shared__ int alias_s[Ldim];
    __shared__ float mk_s[Ldim];
    if (tid < Ldim) { alias_s[tid] = alias[b*Ldim + tid]; mk_s[tid] = mask[b*Ldim + tid]; }
    __syncthreads();
    for (int idx = tid; idx < Ldim*Dn; idx += 256) {
        int l = idx / Dn, c = idx % Dn;
        float v = g_hcomb[((size_t)b*Ldim + alias_s[l])*Dn + c];
        seqs[l][c] = v;
        g_seq[((size_t)b*Ldim + l)*Dn + c] = v;
    }
    __syncthreads();
    if (tid < Dn) {
        float acc = 0.f, msum = 0.f;
        for (int l = 0; l < Ldim; l++) {
            acc = fmaf(seqs[l][tid], mk_s[l], acc);
            msum += mk_s[l];
        }
        hs_s[tid] = acc / msum;
    }
    __syncthreads();
    if (tid < Dn) {
        float t = glu2_b[tid];
        for (int c = 0; c < Dn; c++) t = fmaf(hs_s[c], __ldg(&glu2_w[c*Dn + tid]), t);
        g_hsg[b*Dn + tid] = t;
    }
}

// ---------------- K5b: fused nh + GLU + select (tf32 mma x2) ----------------
#define NS_WA   0        // 200*104 = 20800
#define NS_INS  20800    // 32*204  = 6528  -> 27328
#define NS_NH   27328    // 32*108  = 3456  -> 30784
#define NS_HB   30784    // 104
#define NS_W2   30888    // 104
#define NS_RED  30992    // 32*4 = 128
#define NS_BETA 31120    // 32
#define NS_TOT  31152
__global__ __launch_bounds__(256) void k_nhsel(
    const float* __restrict__ pos_emb, const float* __restrict__ w_1,
    const float* __restrict__ glu1_w, const float* __restrict__ glu1_b,
    const float* __restrict__ w_2, const float* __restrict__ mask)
{
    extern __shared__ float sm[];
    float* wA    = sm + NS_WA;
    float* ins   = sm + NS_INS;
    float* nh    = sm + NS_NH;
    float* hb_s  = sm + NS_HB;
    float* w2s   = sm + NS_W2;
    float* red   = sm + NS_RED;
    float* beta_s= sm + NS_BETA;
    int tid = threadIdx.x;
    int lane = tid & 31, warp = tid >> 5;
    int row0 = blockIdx.x * 32;
    int b = row0 >> 6;
    int lbase = row0 & 63;

    for (int i = tid; i < 200*104; i += 256) wA[i] = 0.f;
    if (tid < 104) {
        hb_s[tid] = (tid < Dn) ? glu1_b[tid] + g_hsg[b*Dn + tid] : 0.f;
        w2s[tid]  = (tid < Dn) ? w_2[tid] : 0.f;
    }
    __syncthreads();
    for (int i = tid; i < 200*100; i += 256) {
        int k = i / 100, n = i % 100;
        wA[k*104 + n] = to_tf32(w_1[i]);
    }
    for (int idx = tid; idx < 32*25; idx += 256) {
        int r = idx / 25, c4 = (idx % 25) * 4;
        size_t row = row0 + r;
        int l = (int)(row % Ldim);
        float4 vp = *(const float4*)(pos_emb + l*Dn + c4);
        float4 vs = *(const float4*)(g_seq + row*Dn + c4);
        float* d = ins + r*204;
        d[c4+0] = to_tf32(vp.x); d[c4+1] = to_tf32(vp.y);
        d[c4+2] = to_tf32(vp.z); d[c4+3] = to_tf32(vp.w);
        d[100+c4+0] = to_tf32(vs.x); d[100+c4+1] = to_tf32(vs.y);
        d[100+c4+2] = to_tf32(vs.z); d[100+c4+3] = to_tf32(vs.w);
    }
    if (tid < 32) {
        float* d = ins + tid*204 + 200;
        d[0] = 0.f; d[1] = 0.f; d[2] = 0.f; d[3] = 0.f;
        float* d2 = nh + tid*108 + 100;
        #pragma unroll
        for (int q = 0; q < 8; q++) d2[q] = 0.f;
    }
    __syncthreads();

    int g = lane >> 2, tg = lane & 3;
    int mt = warp & 1;
    int ng = warp >> 1;
    int rl = mt*16 + g, rh = rl + 8;

    // GEMM1: [32 x 200] @ w_1 -> tanh -> nh
    {
        float acc[4][4];
        #pragma unroll
        for (int j = 0; j < 4; j++)
            #pragma unroll
            for (int q = 0; q < 4; q++) acc[j][q] = 0.f;
        const float* Arow = ins + mt*16*204;
        #pragma unroll 1
        for (int kt = 0; kt < 25; kt++) {
            int ak = kt*8;
            uint32_t a0 = __float_as_uint(Arow[ g   *204 + ak + tg    ]);
            uint32_t a1 = __float_as_uint(Arow[(g+8)*204 + ak + tg    ]);
            uint32_t a2 = __float_as_uint(Arow[ g   *204 + ak + tg + 4]);
            uint32_t a3 = __float_as_uint(Arow[(g+8)*204 + ak + tg + 4]);
            #pragma unroll
            for (int j = 0; j < 4; j++) {
                int nt = ng*4 + j;
                if (nt < 13) {
                    uint32_t b0 = __float_as_uint(wA[(ak + tg    )*104 + nt*8 + g]);
                    uint32_t b1 = __float_as_uint(wA[(ak + tg + 4)*104 + nt*8 + g]);
                    asm volatile(
                        "mma.sync.aligned.m16n8k8.row.col.f32.tf32.tf32.f32 "
                        "{%0,%1,%2,%3}, {%4,%5,%6,%7}, {%8,%9}, {%0,%1,%2,%3};"
                        : "+f"(acc[j][0]), "+f"(acc[j][1]), "+f"(acc[j][2]), "+f"(acc[j][3])
                        : "r"(a0), "r"(a1), "r"(a2), "r"(a3), "r"(b0), "r"(b1));
                }
            }
        }
        #pragma unroll
        for (int j = 0; j < 4; j++) {
            int nt = ng*4 + j;
            if (nt < 13) {
                int c = nt*8 + tg*2;
                if (c < 100) {
                    nh[rl*108 + c] = to_tf32(tanhf(acc[j][0]));
                    nh[rh*108 + c] = to_tf32(tanhf(acc[j][2]));
                }
                if (c + 1 < 100) {
                    nh[rl*108 + c + 1] = to_tf32(tanhf(acc[j][1]));
                    nh[rh*108 + c + 1] = to_tf32(tanhf(acc[j][3]));
                }
            }
        }
    }
    __syncthreads();
    for (int i = tid; i < 104*104; i += 256) wA[i] = 0.f;
    __syncthreads();
    for (int i = tid; i < 100*100; i += 256) {
        int k = i / 100, n = i % 100;
        wA[k*104 + n] = to_tf32(glu1_w[i]);
    }
    __syncthreads();

    // GEMM2: t = nh @ glu1_w; sigmoid(t + hb); beta partials
    {
        float t[4][4];
        #pragma unroll
        for (int j = 0; j < 4; j++)
            #pragma unroll
            for (int q = 0; q < 4; q++) t[j][q] = 0.f;
        const float* A2 = nh + mt*16*108;
        #pragma unroll 1
        for (int kt = 0; kt < 13; kt++) {
            int ak = kt*8;
            uint32_t a0 = __float_as_uint(A2[ g   *108 + ak + tg    ]);
            uint32_t a1 = __float_as_uint(A2[(g+8)*108 + ak + tg    ]);
            uint32_t a2 = __float_as_uint(A2[ g   *108 + ak + tg + 4]);
            uint32_t a3 = __float_as_uint(A2[(g+8)*108 + ak + tg + 4]);
            #pragma unroll
            for (int j = 0; j < 4; j++) {
                int nt = ng*4 + j;
                if (nt < 13) {
                    uint32_t b0 = __float_as_uint(wA[(ak + tg    )*104 + nt*8 + g]);
                    uint32_t b1 = __float_as_uint(wA[(ak + tg + 4)*104 + nt*8 + g]);
                    asm volatile(
                        "mma.sync.aligned.m16n8k8.row.col.f32.tf32.tf32.f32 "
                        "{%0,%1,%2,%3}, {%4,%5,%6,%7}, {%8,%9}, {%0,%1,%2,%3};"
                        : "+f"(t[j][0]), "+f"(t[j][1]), "+f"(t[j][2]), "+f"(t[j][3])
                        : "r"(a0), "r"(a1), "r"(a2), "r"(a3), "r"(b0), "r"(b1));
                }
            }
        }
        float p_lo = 0.f, p_hi = 0.f;
        #pragma unroll
        for (int j = 0; j < 4; j++) {
            int nt = ng*4 + j;
            if (nt < 13) {
                int c = nt*8 + tg*2;
                if (c < 100) {
                    float s0 = 1.f / (1.f + __expf(-(t[j][0] + hb_s[c])));
                    float s2 = 1.f / (1.f + __expf(-(t[j][2] + hb_s[c])));
                    p_lo = fmaf(s0, w2s[c], p_lo);
                    p_hi = fmaf(s2, w2s[c], p_hi);
                }
                if (c + 1 < 100) {
                    float s1 = 1.f / (1.f + __expf(-(t[j][1] + hb_s[c+1])));
                    float s3 = 1.f / (1.f + __expf(-(t[j][3] + hb_s[c+1])));
                    p_lo = fmaf(s1, w2s[c+1], p_lo);
                    p_hi = fmaf(s3, w2s[c+1], p_hi);
                }
            }
        }
        p_lo += __shfl_xor_sync(0xffffffffu, p_lo, 1);
        p_lo += __shfl_xor_sync(0xffffffffu, p_lo, 2);
        p_hi += __shfl_xor_sync(0xffffffffu, p_hi, 1);
        p_hi += __shfl_xor_sync(0xffffffffu, p_hi, 2);
        if (tg == 0) {
            red[rl*4 + ng] = p_lo;
            red[rh*4 + ng] = p_hi;
        }
    }
    __syncthreads();
    if (tid < 32) {
        float s = red[tid*4] + red[tid*4+1] + red[tid*4+2] + red[tid*4+3];
        beta_s[tid] = s * mask[b*Ldim + lbase + tid];
    }
    __syncthreads();

    if (tid < Dn) {
        float sel = 0.f;
        #pragma unroll 8
        for (int r = 0; r < 32; r++)
            sel = fmaf(beta_s[r], ins[r*204 + 100 + tid], sel);
        g_selpart[blockIdx.x*Dn + tid] = sel;
    }
}

// ---------------- K6a: score (tf32 mma, 64-row batch tile) ------------------
#define SC_EMB  6656          // after sel_s 64*104
#define SC_TOT  (6656 + 128*104)   // 19968 floats
__global__ __launch_bounds__(256) void k_score(
    const float* __restrict__ emb, float* __restrict__ out)
{
    extern __shared__ float sm[];
    float* sel_s = sm;
    float* emb_s = sm + SC_EMB;
    int n0 = blockIdx.x * 128, b0 = blockIdx.y * 64;
    int tid = threadIdx.x;
    int lane = tid & 31, warp = tid >> 5;

    for (int idx = tid; idx < 64*25; idx += 256) {
        int r = idx / 25, c4 = (idx % 25) * 4;
        int bb = b0 + r;
        float4 v0 = *(const float4*)(g_selpart + (2*bb)*Dn + c4);
        float4 v1 = *(const float4*)(g_selpart + (2*bb+1)*Dn + c4);
        float* d = sel_s + r*104 + c4;
        d[0] = to_tf32(v0.x + v1.x); d[1] = to_tf32(v0.y + v1.y);
        d[2] = to_tf32(v0.z + v1.z); d[3] = to_tf32(v0.w + v1.w);
    }
    if (tid < 64) {
        float* d = sel_s + tid*104 + 100;
        d[0] = 0.f; d[1] = 0.f; d[2] = 0.f; d[3] = 0.f;
    }
    for (int idx = tid; idx < 128*25; idx += 256) {
        int r = idx / 25, c4 = (idx % 25) * 4;
        int n = n0 + r;
        float4 v = make_float4(0.f,0.f,0.f,0.f);
        if (n < NOUT) v = *(const float4*)(emb + (size_t)(n + 1)*Dn + c4);
        float* d = emb_s + r*104 + c4;
        d[0] = to_tf32(v.x); d[1] = to_tf32(v.y);
        d[2] = to_tf32(v.z); d[3] = to_tf32(v.w);
    }
    if (tid < 128) {
        float* d = emb_s + tid*104 + 100;
        d[0] = 0.f; d[1] = 0.f; d[2] = 0.f; d[3] = 0.f;
    }
    __syncthreads();

    int g = lane >> 2, tg = lane & 3;
    int mt = warp & 3;            // 4 m-tiles of 16 rows
    int nb = warp >> 2;           // 2 n-groups of 8 n-tiles
    const float* Arow = sel_s + mt*16*104;

    float acc[8][4];
    #pragma unroll
    for (int j = 0; j < 8; j++)
        #pragma unroll
        for (int q = 0; q < 4; q++) acc[j][q] = 0.f;

    #pragma unroll 1
    for (int kt = 0; kt < 13; kt++) {
        int ak = kt*8;
        uint32_t a0 = __float_as_uint(Arow[ g   *104 + ak + tg    ]);
        uint32_t a1 = __float_as_uint(Arow[(g+8)*104 + ak + tg    ]);
        uint32_t a2 = __float_as_uint(Arow[ g   *104 + ak + tg + 4]);
        uint32_t a3 = __float_as_uint(Arow[(g+8)*104 + ak + tg + 4]);
        #pragma unroll
        for (int j = 0; j < 8; j++) {
            int nt = nb*8 + j;
            uint32_t bb0 = __float_as_uint(emb_s[(nt*8 + g)*104 + ak + tg    ]);
            uint32_t bb1 = __float_as_uint(emb_s[(nt*8 + g)*104 + ak + tg + 4]);
            asm volatile(
                "mma.sync.aligned.m16n8k8.row.col.f32.tf32.tf32.f32 "
                "{%0,%1,%2,%3}, {%4,%5,%6,%7}, {%8,%9}, {%0,%1,%2,%3};"
                : "+f"(acc[j][0]), "+f"(acc[j][1]), "+f"(acc[j][2]), "+f"(acc[j][3])
                : "r"(a0), "r"(a1), "r"(a2), "r"(a3), "r"(bb0), "r"(bb1));
        }
    }

    int row_lo = b0 + mt*16 + g;
    int row_hi = row_lo + 8;
    float rmax_lo = -3.0e38f, rmax_hi = -3.0e38f;
    #pragma unroll
    for (int j = 0; j < 8; j++) {
        int nt = nb*8 + j;
        int ncol = n0 + nt*8 + tg*2;
        if (ncol < NOUT) {
            out[(size_t)row_lo*NOUT + ncol] = acc[j][0];
            out[(size_t)row_hi*NOUT + ncol] = acc[j][2];
            rmax_lo = fmaxf(rmax_lo, acc[j][0]);
            rmax_hi = fmaxf(rmax_hi, acc[j][2]);
        }
        if (ncol + 1 < NOUT) {
            out[(size_t)row_lo*NOUT + ncol + 1] = acc[j][1];
            out[(size_t)row_hi*NOUT + ncol + 1] = acc[j][3];
            rmax_lo = fmaxf(rmax_lo, acc[j][1]);
            rmax_hi = fmaxf(rmax_hi, acc[j][3]);
        }
    }
    rmax_lo = fmaxf(rmax_lo, __shfl_xor_sync(0xffffffffu, rmax_lo, 1));
    rmax_lo = fmaxf(rmax_lo, __shfl_xor_sync(0xffffffffu, rmax_lo, 2));
    rmax_hi = fmaxf(rmax_hi, __shfl_xor_sync(0xffffffffu, rmax_hi, 1));
    rmax_hi = fmaxf(rmax_hi, __shfl_xor_sync(0xffffffffu, rmax_hi, 2));
    if (tg == 0) {
        atomicMax(&g_rmaxbits[row_lo], fkey(rmax_lo));
        atomicMax(&g_rmaxbits[row_hi], fkey(rmax_hi));
    }
}

// ---------------- K6b: per-chunk sum of exp ----------------
__global__ __launch_bounds__(256) void k_expsum(const float* __restrict__ out)
{
    int b = blockIdx.y, chunk = blockIdx.x, tid = threadIdx.x;
    int start = chunk * CHUNKSZ;
    int end = start + CHUNKSZ; if (end > NOUT) end = NOUT;
    float m = funkey(g_rmaxbits[b]);
    float s = 0.f;
    for (int n = start + tid; n < end; n += 256)
        s += fexp(out[(size_t)b*NOUT + n] - m);
    __shared__ float red[256];
    red[tid] = s;
    __syncthreads();
    for (int st = 128; st > 0; st >>= 1) {
        if (tid < st) red[tid] += red[tid + st];
        __syncthreads();
    }
    if (tid == 0) g_rpart[b*NCHUNK + chunk] = red[0];
}

// ---------------- K6c: exp + scale ----------------
__global__ __launch_bounds__(256) void k_scale(float* __restrict__ out)
{
    int b = blockIdx.y;
    int n = blockIdx.x * 256 + threadIdx.x;
    if (n < NOUT) {
        float ssum = 0.f;
        #pragma unroll
        for (int j = 0; j < NCHUNK; j++) ssum += g_rpart[b*NCHUNK + j];
        float m = funkey(g_rmaxbits[b]);
        float inv = __fdividef(1.f, ssum);
        size_t idx = (size_t)b*NOUT + n;
        out[idx] = fexp(out[idx] - m) * inv;
    }
}

// ---------------- launch ----------------
extern "C" void kernel_launch(void* const* d_in, const int* in_sizes, int n_in,
                              void* d_out, int out_size)
{
    const int*   alias_inputs = (const int*)  d_in[0];
    const int*   items        = (const int*)  d_in[1];
    const int*   adj          = (const int*)  d_in[2];
    const float* mask_item    = (const float*)d_in[3];
    const int*   seq_features = (const int*)  d_in[4];
    const int*   adj_all      = (const int*)  d_in[5];
    const float* num_w        = (const float*)d_in[6];
    const float* emb          = (const float*)d_in[7];
    const float* pos_emb      = (const float*)d_in[8];
    const float* a0           = (const float*)d_in[9];
    const float* a1           = (const float*)d_in[10];
    const float* a2           = (const float*)d_in[11];
    const float* a3           = (const float*)d_in[12];
    const float* g_w1         = (const float*)d_in[13];
    const float* g_w2         = (const float*)d_in[14];
    const float* g_w3         = (const float*)d_in[15];
    const float* w_1          = (const float*)d_in[16];
    const float* w_2          = (const float*)d_in[17];
    const float* glu1_w       = (const float*)d_in[18];
    const float* glu1_b       = (const float*)d_in[19];
    const float* glu2_w       = (const float*)d_in[20];
    const float* glu2_b       = (const float*)d_in[21];
    float* out = (float*)d_out;

    static cudaStream_t s2 = nullptr;
    static cudaEvent_t ev_fork = nullptr, ev_join = nullptr;
    static bool attr_done = false;
    if (!s2) {
        cudaStreamCreateWithFlags(&s2, cudaStreamNonBlocking);
        cudaEventCreateWithFlags(&ev_fork, cudaEventDisableTiming);
        cudaEventCreateWithFlags(&ev_join, cudaEventDisableTiming);
    }

    const int GSMEM = GT_TOT * 4;                  // ~86.3 KB
    const int CSMEM = CB_TOT * 4;                  // ~109.3 KB
    const int NSMEM = NS_TOT * 4;                  // ~124.6 KB
    const int SSMEM = SC_TOT * 4;                  // ~79.9 KB
    if (!attr_done) {
        cudaFuncSetAttribute(k_global,  cudaFuncAttributeMaxDynamicSharedMemorySize, GSMEM);
        cudaFuncSetAttribute(k_combine, cudaFuncAttributeMaxDynamicSharedMemorySize, CSMEM);
        cudaFuncSetAttribute(k_nhsel,   cudaFuncAttributeMaxDynamicSharedMemorySize, NSMEM);
        cudaFuncSetAttribute(k_score,   cudaFuncAttributeMaxDynamicSharedMemorySize, SSMEM);
        attr_done = true;
    }

    k_init   <<<1, 256>>>();
    cudaEventRecord(ev_fork, 0);
    cudaStreamWaitEvent(s2, ev_fork, 0);
    k_local  <<<Bn*2, 256, 0, s2>>>(items, adj, emb, a0, a1, a2, a3);
    k_global <<<Bn*2, 256, GSMEM>>>(items, adj_all, num_w, emb, g_w1, g_w2,
                                    seq_features, mask_item);
    cudaEventRecord(ev_join, s2);
    cudaStreamWaitEvent(0, ev_join, 0);
    k_combine<<<(Bn*Ldim)/64, 256, CSMEM>>>(g_w3);
    k_seqhs  <<<Bn, 256>>>(alias_inputs, mask_item, glu2_w, glu2_b);
    k_nhsel  <<<(Bn*Ldim)/32, 256, NSMEM>>>(pos_emb, w_1, glu1_w, glu1_b, w_2, mask_item);
    dim3 gs((NOUT + 127)/128, Bn/64);
    k_score  <<<gs, 256, SSMEM>>>(emb, out);
    dim3 ge(NCHUNK, Bn);
    k_expsum <<<ge, 256>>>(out);
    dim3 gn((NOUT + 255)/256, Bn);
    k_scale  <<<gn, 256>>>(out);
}

// round 17
// speedup vs baseline: 1.0666x; 1.0449x over previous
#include <cuda_runtime.h>
#include <math.h>
#include <stdint.h>

#define Bn 256
#define Ldim 64
#define Sn 12
#define Dn 100
#define NUM_NODE 43098
#define NOUT 43097
#define NEGV -9000000000000000.0f
#define NCHUNK 8
#define CHUNKSZ 5388   // ceil(43097/8)

// ---------------- scratch (device globals; no allocation) ----------------
__device__ float g_h[Bn*Ldim*Dn];
__device__ float g_hlocal[Bn*Ldim*Dn];
__device__ float g_nb[Bn*Ldim*Dn];
__device__ float g_seq[Bn*Ldim*Dn];
__device__ float g_hsg[Bn*Dn];
__device__ float g_selpart[2*Bn*Dn];
__device__ unsigned g_rmaxbits[Bn];
__device__ float g_rpart[Bn*NCHUNK];

__device__ __forceinline__ unsigned fkey(float f) {
    unsigned u = __float_as_uint(f);
    return (u & 0x80000000u) ? ~u : (u | 0x80000000u);
}
__device__ __forceinline__ float funkey(unsigned k) {
    return (k & 0x80000000u) ? __uint_as_float(k ^ 0x80000000u)
                             : __uint_as_float(~k);
}

__device__ __forceinline__ float fexp(float x) {
    float y = x * 1.44269504088896340736f;
    y = fmaxf(y, -126.0f);
    float t = y + 12582912.0f;
    float i = t - 12582912.0f;
    float f = y - i;
    int ii = (int)i;
    float p = 1.54035303933816e-4f;
    p = fmaf(p, f, 1.33335581464284e-3f);
    p = fmaf(p, f, 9.61812910762848e-3f);
    p = fmaf(p, f, 5.55041086648216e-2f);
    p = fmaf(p, f, 2.40226506959101e-1f);
    p = fmaf(p, f, 6.93147180559945e-1f);
    p = fmaf(p, f, 1.0f);
    return p * __int_as_float((ii + 127) << 23);
}

__device__ __forceinline__ float to_tf32(float x) {
    uint32_t r;
    asm("cvt.rna.tf32.f32 %0, %1;" : "=r"(r) : "f"(x));
    return __uint_as_float(r);
}

// ---------------- K0 ----------------
__global__ void k_init() {
    int t = threadIdx.x;
    if (t < Bn) g_rmaxbits[t] = 0u;
}

// ---------------- K1: local graph attention (float4, 2 CTAs/row) -----------
__global__ __launch_bounds__(256) void k_local(
    const int* __restrict__ items, const int* __restrict__ adj,
    const float* __restrict__ emb,
    const float* __restrict__ a0, const float* __restrict__ a1,
    const float* __restrict__ a2, const float* __restrict__ a3)
{
    int b = blockIdx.x >> 1;
    int half = blockIdx.x & 1;
    int i0 = half * 32;
    __shared__ float hs[Ldim][108];
    __shared__ float alpha[32][Ldim+1];
    __shared__ float At[4][108];
    int tid = threadIdx.x;

    for (int i = tid; i < Dn; i += 256) {
        At[0][i] = a0[i]; At[1][i] = a1[i]; At[2][i] = a2[i]; At[3][i] = a3[i];
    }
    for (int idx = tid; idx < Ldim*25; idx += 256) {
        int l = idx / 25, c4 = (idx % 25) * 4;
        float4 v = *(const float4*)(emb + (size_t)items[b*Ldim + l]*Dn + c4);
        *(float4*)(&hs[l][c4]) = v;
    }
    __syncthreads();
    for (int idx = tid; idx < 32*25; idx += 256) {
        int l = i0 + idx / 25, c4 = (idx % 25) * 4;
        *(float4*)(g_h + ((size_t)b*Ldim + l)*Dn + c4) = *(const float4*)(&hs[l][c4]);
    }

    for (int p = tid; p < 32*Ldim; p += 256) {
        int il = p >> 6, j = p & 63;
        int i = i0 + il;
        int a = adj[((size_t)b*Ldim + i)*Ldim + j];
        float val = NEGV;
        if (a >= 1 && a <= 4) {
            int k = a - 1;
            const float4* hi = (const float4*)hs[i];
            const float4* hj = (const float4*)hs[j];
            const float4* at = (const float4*)At[k];
            float acc = 0.f;
            #pragma unroll 5
            for (int d4 = 0; d4 < 25; d4++) {
                float4 x = hi[d4], y = hj[d4], w = at[d4];
                acc = fmaf(x.x*y.x, w.x, acc);
                acc = fmaf(x.y*y.y, w.y, acc);
                acc = fmaf(x.z*y.z, w.z, acc);
                acc = fmaf(x.w*y.w, w.w, acc);
            }
            val = acc > 0.f ? acc : 0.2f * acc;
        }
        alpha[il][j] = val;
    }
    __syncthreads();

    int warp = tid >> 5, lane = tid & 31;
    for (int il = warp; il < 32; il += 8) {
        float x0 = alpha[il][lane], x1 = alpha[il][lane+32];
        float m = fmaxf(x0, x1);
        #pragma unroll
        for (int o = 16; o > 0; o >>= 1) m = fmaxf(m, __shfl_xor_sync(0xffffffffu, m, o));
        float e0 = __expf(fmaxf(x0 - m, -87.f));
        float e1 = __expf(fmaxf(x1 - m, -87.f));
        float s = e0 + e1;
        #pragma unroll
        for (int o = 16; o > 0; o >>= 1) s += __shfl_xor_sync(0xffffffffu, s, o);
        float inv = 1.f / s;
        alpha[il][lane] = e0 * inv;
        alpha[il][lane+32] = e1 * inv;
    }
    __syncthreads();

    for (int idx = tid; idx < 32*25; idx += 256) {
        int il = idx / 25, c4 = (idx % 25) * 4;
        float ax = 0.f, ay = 0.f, az = 0.f, aw = 0.f;
        for (int j = 0; j < Ldim; j++) {
            float al = alpha[il][j];
            float4 v = *(const float4*)(&hs[j][c4]);
            ax = fmaf(al, v.x, ax);
            ay = fmaf(al, v.y, ay);
            az = fmaf(al, v.z, az);
            aw = fmaf(al, v.w, aw);
        }
        *(float4*)(g_hlocal + ((size_t)b*Ldim + i0 + il)*Dn + c4)
            = make_float4(ax, ay, az, aw);
    }
}

// ---------------- K3: global neighbor aggregation (tf32 mma; in-CTA sess) --
#define GT_W1   0        // 104*104 = 10816
#define GT_FEAT 10816    // 96*108  = 10368
#define GT_W2   21184    // 104
#define GT_SESS 21288    // 100
#define GT_ALSC 21388    // 96
#define GT_NBR  21484    // 96 ints
#define GT_TOT  21580
__global__ __launch_bounds__(256, 2) void k_global(
    const int* __restrict__ items, const int* __restrict__ adj_all,
    const float* __restrict__ num_w, const float* __restrict__ emb,
    const float* __restrict__ g_w1, const float* __restrict__ g_w2,
    const int* __restrict__ seq_features, const float* __restrict__ mask)
{
    extern __shared__ float sm[];
    float* w1s   = sm + GT_W1;
    float* feat  = sm + GT_FEAT;
    float* w2s   = sm + GT_W2;
    float* sesss = sm + GT_SESS;
    float* alsc  = sm + GT_ALSC;
    int*   nbrs  = (int*)(sm + GT_NBR);

    int blk = blockIdx.x;
    int b = blk >> 1;
    int l0 = (blk & 1) * 32;
    int tid = threadIdx.x;
    int lane = tid & 31, warp = tid >> 5;

    for (int i = tid; i < 104*104; i += 256) w1s[i] = 0.f;
    if (tid < 104) w2s[tid] = (tid < Dn) ? g_w2[tid] : 0.f;
    if (tid < Ldim) alsc[tid] = mask[b*Ldim + tid];
    for (int idx = tid; idx < Ldim*25; idx += 256) {
        int r = idx / 25, c4 = (idx % 25) * 4;
        float4 v = *(const float4*)(emb + (size_t)seq_features[b*Ldim + r]*Dn + c4);
        *(float4*)(feat + r*108 + c4) = v;
    }
    __syncthreads();
    if (tid < Dn) {
        float s = 0.f, ms = 0.f;
        for (int l = 0; l < Ldim; l++) {
            s = fmaf(feat[l*108 + tid], alsc[l], s);
            ms += alsc[l];
        }
        sesss[tid] = s / ms;
    }
    __syncthreads();
    for (int i = tid; i < 101*100; i += 256) {
        int k = i / 100, n = i % 100;
        float scale = (k < 100) ? sesss[k] : 1.f;
        w1s[k*104 + n] = to_tf32(g_w1[i] * scale);
    }
    __syncthreads();

    int g = lane >> 2, tg = lane & 3;

    for (int it = 0; it < 4; it++) {
        int lbase = l0 + it*8;
        if (tid < 96) {
            int l = tid / 12, s = tid % 12;
            int node = items[b*Ldim + lbase + l];
            nbrs[tid] = adj_all[(size_t)node*Sn + s];
            feat[tid*108 + 100] = to_tf32(num_w[(size_t)node*Sn + s]);
            feat[tid*108 + 101] = 0.f;
            feat[tid*108 + 102] = 0.f;
            feat[tid*108 + 103] = 0.f;
        }
        for (int idx = tid; idx < 96*25; idx += 256) {
            int r = idx / 25, c4 = (idx % 25) * 4;
            int node = items[b*Ldim + lbase + r/12];
            int nbr  = adj_all[(size_t)node*Sn + (r%12)];
            float4 e = *(const float4*)(emb + (size_t)nbr*Dn + c4);
            float* dst = feat + r*108 + c4;
            dst[0] = to_tf32(e.x);
            dst[1] = to_tf32(e.y);
            dst[2] = to_tf32(e.z);
            dst[3] = to_tf32(e.w);
        }
        __syncthreads();

        if (warp < 6) {
            const float* Ab = feat + warp*16*108;
            float acc[13][4];
            #pragma unroll
            for (int nt = 0; nt < 13; nt++)
                #pragma unroll
                for (int q = 0; q < 4; q++) acc[nt][q] = 0.f;

            #pragma unroll 1
            for (int kt = 0; kt < 13; kt++) {
                int ak = kt*8;
                uint32_t a0 = __float_as_uint(Ab[ g   *108 + ak + tg    ]);
                uint32_t a1 = __float_as_uint(Ab[(g+8)*108 + ak + tg    ]);
                uint32_t a2 = __float_as_uint(Ab[ g   *108 + ak + tg + 4]);
                uint32_t a3 = __float_as_uint(Ab[(g+8)*108 + ak + tg + 4]);
                const float* wrow0 = w1s + (ak + tg)*104;
                const float* wrow1 = w1s + (ak + tg + 4)*104;
                #pragma unroll
                for (int nt = 0; nt < 13; nt++) {
                    uint32_t b0 = __float_as_uint(wrow0[nt*8 + g]);
                    uint32_t b1 = __float_as_uint(wrow1[nt*8 + g]);
                    asm volatile(
                        "mma.sync.aligned.m16n8k8.row.col.f32.tf32.tf32.f32 "
                        "{%0,%1,%2,%3}, {%4,%5,%6,%7}, {%8,%9}, {%0,%1,%2,%3};"
                        : "+f"(acc[nt][0]), "+f"(acc[nt][1]), "+f"(acc[nt][2]), "+f"(acc[nt][3])
                        : "r"(a0), "r"(a1), "r"(a2), "r"(a3), "r"(b0), "r"(b1));
                }
            }

            float score_a = 0.f, score_b = 0.f;
            #pragma unroll
            for (int nt = 0; nt < 13; nt++) {
                int j0 = nt*8 + tg*2;
                float w20 = w2s[j0], w21 = w2s[j0+1];
                float v0 = acc[nt][0] > 0.f ? acc[nt][0] : 0.2f*acc[nt][0];
                float v1 = acc[nt][1] > 0.f ? acc[nt][1] : 0.2f*acc[nt][1];
                float v2 = acc[nt][2] > 0.f ? acc[nt][2] : 0.2f*acc[nt][2];
                float v3 = acc[nt][3] > 0.f ? acc[nt][3] : 0.2f*acc[nt][3];
                score_a = fmaf(v0, w20, fmaf(v1, w21, score_a));
                score_b = fmaf(v2, w20, fmaf(v3, w21, score_b));
            }
            score_a += __shfl_xor_sync(0xffffffffu, score_a, 1);
            score_a += __shfl_xor_sync(0xffffffffu, score_a, 2);
            score_b += __shfl_xor_sync(0xffffffffu, score_b, 1);
            score_b += __shfl_xor_sync(0xffffffffu, score_b, 2);
            if (tg == 0) {
                alsc[warp*16 + g]     = score_a;
                alsc[warp*16 + g + 8] = score_b;
            }
        }
        __syncthreads();

        if (tid < 8) {
            float* a = alsc + tid*12;
            float m = a[0];
            #pragma unroll
            for (int s = 1; s < Sn; s++) m = fmaxf(m, a[s]);
            float ssum = 0.f;
            float e[Sn];
            #pragma unroll
            for (int s = 0; s < Sn; s++) { e[s] = __expf(a[s] - m); ssum += e[s]; }
            float inv = 1.f / ssum;
            #pragma unroll
            for (int s = 0; s < Sn; s++) a[s] = e[s] * inv;
        }
        __syncthreads();

        for (int idx = tid; idx < 800; idx += 256) {
            int l = idx / 100, c = idx % 100;
            const float* fr = feat + (l*12)*108 + c;
            const float* al = alsc + l*12;
            float acc2 = 0.f;
            #pragma unroll
            for (int s = 0; s < Sn; s++)
                acc2 = fmaf(al[s], fr[s*108], acc2);
            g_nb[((size_t)b*Ldim + lbase + l)*Dn + c] = acc2;
        }
        __syncthreads();
    }
}

// ---------------- K4: fused h_combine + seqhs (tf32 mma) --------------------
// CTA = one batch row (64 l). smem: w3s[200*104] + ins[6528] (reused as hcomb
// [64][102] after GEMMs) + alias/mask/hs
#define CB_W3   0            // 200*104 = 20800
#define CB_INS  20800        // 6528 (ins 32x204, then hcomb 64x102)
#define CB_HS   27328        // 104
#define CB_MK   27432        // 64
#define CB_ALIA 27496        // 64 ints
#define CB_TOT  27560
__global__ __launch_bounds__(256) void k_combseq(
    const float* __restrict__ g_w3,
    const int* __restrict__ alias, const float* __restrict__ mask,
    const float* __restrict__ glu2_w, const float* __restrict__ glu2_b)
{
    extern __shared__ float sm[];
    float* w3s   = sm + CB_W3;
    float* ins   = sm + CB_INS;
    float* hs_s  = sm + CB_HS;
    float* mk_s  = sm + CB_MK;
    int*   alias_s = (int*)(sm + CB_ALIA);
    int tid = threadIdx.x;
    int lane = tid & 31, warp = tid >> 5;
    int b = blockIdx.x;

    for (int i = tid; i < 200*104; i += 256) w3s[i] = 0.f;
    if (tid < Ldim) {
        alias_s[tid] = alias[b*Ldim + tid];
        mk_s[tid] = mask[b*Ldim + tid];
    }
    __syncthreads();
    for (int i = tid; i < 200*100; i += 256) {
        int k = i / 100, n = i % 100;
        w3s[k*104 + n] = to_tf32(g_w3[i]);
    }

    int g = lane >> 2, tg = lane & 3;
    int mt = warp & 1;
    int ng = warp >> 1;

    float accA[4][4], accB[4][4];   // iteration 0 / 1 accumulators
    #pragma unroll
    for (int j = 0; j < 4; j++)
        #pragma unroll
        for (int q = 0; q < 4; q++) { accA[j][q] = 0.f; accB[j][q] = 0.f; }

    for (int it = 0; it < 2; it++) {
        int row0 = b * 64 + it * 32;
        __syncthreads();
        for (int idx = tid; idx < 32*25; idx += 256) {
            int r = idx / 25, c4 = (idx % 25) * 4;
            size_t row = row0 + r;
            float4 vh = *(const float4*)(g_h  + row*Dn + c4);
            float4 vn = *(const float4*)(g_nb + row*Dn + c4);
            float* d = ins + r*204;
            d[c4+0]   = to_tf32(vh.x); d[c4+1]   = to_tf32(vh.y);
            d[c4+2]   = to_tf32(vh.z); d[c4+3]   = to_tf32(vh.w);
            d[100+c4+0] = to_tf32(vn.x); d[100+c4+1] = to_tf32(vn.y);
            d[100+c4+2] = to_tf32(vn.z); d[100+c4+3] = to_tf32(vn.w);
        }
        if (tid < 32) {
            float* d = ins + tid*204 + 200;
            d[0] = 0.f; d[1] = 0.f; d[2] = 0.f; d[3] = 0.f;
        }
        __syncthreads();

        const float* Arow = ins + mt*16*204;
        #pragma unroll 1
        for (int kt = 0; kt < 25; kt++) {
            int ak = kt*8;
            uint32_t a0 = __float_as_uint(Arow[ g   *204 + ak + tg    ]);
            uint32_t a1 = __float_as_uint(Arow[(g+8)*204 + ak + tg    ]);
            uint32_t a2 = __float_as_uint(Arow[ g   *204 + ak + tg + 4]);
            uint32_t a3 = __float_as_uint(Arow[(g+8)*204 + ak + tg + 4]);
            #pragma unroll
            for (int j = 0; j < 4; j++) {
                int nt = ng*4 + j;
                if (nt < 13) {
                    uint32_t b0 = __float_as_uint(w3s[(ak + tg    )*104 + nt*8 + g]);
                    uint32_t b1 = __float_as_uint(w3s[(ak + tg + 4)*104 + nt*8 + g]);
                    if (it == 0) {
                        asm volatile(
                            "mma.sync.aligned.m16n8k8.row.col.f32.tf32.tf32.f32 "
                            "{%0,%1,%2,%3}, {%4,%5,%6,%7}, {%8,%9}, {%0,%1,%2,%3};"
                            : "+f"(accA[j][0]), "+f"(accA[j][1]), "+f"(accA[j][2]), "+f"(accA[j][3])
                            : "r"(a0), "r"(a1), "r"(a2), "r"(a3), "r"(b0), "r"(b1));
                    } else {
                        asm volatile(
                            "mma.sync.aligned.m16n8k8.row.col.f32.tf32.tf32.f32 "
                            "{%0,%1,%2,%3}, {%4,%5,%6,%7}, {%8,%9}, {%0,%1,%2,%3};"
                            : "+f"(accB[j][0]), "+f"(accB[j][1]), "+f"(accB[j][2]), "+f"(accB[j][3])
                            : "r"(a0), "r"(a1), "r"(a2), "r"(a3), "r"(b0), "r"(b1));
                    }
                }
            }
        }
    }
    __syncthreads();

    // write hcomb = hlocal + relu(acc) into ins reused as [64][102]
    float* hc = ins;
    #pragma unroll
    for (int it = 0; it < 2; it++) {
        int rl = it*32 + mt*16 + g;
        int rh = rl + 8;
        size_t row_lo = (size_t)b*64 + rl;
        size_t row_hi = (size_t)b*64 + rh;
        #pragma unroll
        for (int j = 0; j < 4; j++) {
            int nt = ng*4 + j;
            if (nt < 13) {
                int c = nt*8 + tg*2;
                float v0 = it == 0 ? accA[j][0] : accB[j][0];
                float v1 = it == 0 ? accA[j][1] : accB[j][1];
                float v2 = it == 0 ? accA[j][2] : accB[j][2];
                float v3 = it == 0 ? accA[j][3] : accB[j][3];
                if (c < 100) {
                    hc[rl*102 + c] = g_hlocal[row_lo*Dn + c] + fmaxf(v0, 0.f);
                    hc[rh*102 + c] = g_hlocal[row_hi*Dn + c] + fmaxf(v2, 0.f);
                }
                if (c + 1 < 100) {
                    hc[rl*102 + c + 1] = g_hlocal[row_lo*Dn + c + 1] + fmaxf(v1, 0.f);
                    hc[rh*102 + c + 1] = g_hlocal[row_hi*Dn + c + 1] + fmaxf(v3, 0.f);
                }
            }
        }
    }
    __syncthreads();

    // seqhs: gather by alias -> g_seq; masked mean -> hs; glu2 -> g_hsg
    for (int idx = tid; idx < Ldim*Dn; idx += 256) {
        int l = idx / Dn, c = idx % Dn;
        g_seq[((size_t)b*Ldim + l)*Dn + c] = hc[alias_s[l]*102 + c];
    }
    if (tid < Dn) {
        float acc = 0.f, msum = 0.f;
        for (int l = 0; l < Ldim; l++) {
            acc = fmaf(hc[alias_s[l]*102 + tid], mk_s[l], acc);
            msum += mk_s[l];
        }
        hs_s[tid] = acc / msum;
    }
    __syncthreads();
    if (tid < Dn) {
        float t = glu2_b[tid];
        for (int c = 0; c < Dn; c++) t = fmaf(hs_s[c], __ldg(&glu2_w[c*Dn + tid]), t);
        g_hsg[b*Dn + tid] = t;
    }
}

// ---------------- K5b: fused nh + GLU + select (tf32 mma x2) ----------------
#define NS_WA   0        // 200*104 = 20800
#define NS_INS  20800    // 32*204  = 6528  -> 27328
#define NS_NH   27328    // 32*108  = 3456  -> 30784
#define NS_HB   30784    // 104
#define NS_W2   30888    // 104
#define NS_RED  30992    // 32*4 = 128
#define NS_BETA 31120    // 32
#define NS_TOT  31152
__global__ __launch_bounds__(256) void k_nhsel(
    const float* __restrict__ pos_emb, const float* __restrict__ w_1,
    const float* __restrict__ glu1_w, const float* __restrict__ glu1_b,
    const float* __restrict__ w_2, const float* __restrict__ mask)
{
    extern __shared__ float sm[];
    float* wA    = sm + NS_WA;
    float* ins   = sm + NS_INS;
    float* nh    = sm + NS_NH;
    float* hb_s  = sm + NS_HB;
    float* w2s   = sm + NS_W2;
    float* red   = sm + NS_RED;
    float* beta_s= sm + NS_BETA;
    int tid = threadIdx.x;
    int lane = tid & 31, warp = tid >> 5;
    int row0 = blockIdx.x * 32;
    int b = row0 >> 6;
    int lbase = row0 & 63;

    for (int i = tid; i < 200*104; i += 256) wA[i] = 0.f;
    if (tid < 104) {
        hb_s[tid] = (tid < Dn) ? glu1_b[tid] + g_hsg[b*Dn + tid] : 0.f;
        w2s[tid]  = (tid < Dn) ? w_2[tid] : 0.f;
    }
    __syncthreads();
    for (int i = tid; i < 200*100; i += 256) {
        int k = i / 100, n = i % 100;
        wA[k*104 + n] = to_tf32(w_1[i]);
    }
    for (int idx = tid; idx < 32*25; idx += 256) {
        int r = idx / 25, c4 = (idx % 25) * 4;
        size_t row = row0 + r;
        int l = (int)(row % Ldim);
        float4 vp = *(const float4*)(pos_emb + l*Dn + c4);
        float4 vs = *(const float4*)(g_seq + row*Dn + c4);
        float* d = ins + r*204;
        d[c4+0] = to_tf32(vp.x); d[c4+1] = to_tf32(vp.y);
        d[c4+2] = to_tf32(vp.z); d[c4+3] = to_tf32(vp.w);
        d[100+c4+0] = to_tf32(vs.x); d[100+c4+1] = to_tf32(vs.y);
        d[100+c4+2] = to_tf32(vs.z); d[100+c4+3] = to_tf32(vs.w);
    }
    if (tid < 32) {
        float* d = ins + tid*204 + 200;
        d[0] = 0.f; d[1] = 0.f; d[2] = 0.f; d[3] = 0.f;
        float* d2 = nh + tid*108 + 100;
        #pragma unroll
        for (int q = 0; q < 8; q++) d2[q] = 0.f;
    }
    __syncthreads();

    int g = lane >> 2, tg = lane & 3;
    int mt = warp & 1;
    int ng = warp >> 1;
    int rl = mt*16 + g, rh = rl + 8;

    // GEMM1: [32 x 200] @ w_1 -> tanh -> nh
    {
        float acc[4][4];
        #pragma unroll
        for (int j = 0; j < 4; j++)
            #pragma unroll
            for (int q = 0; q < 4; q++) acc[j][q] = 0.f;
        const float* Arow = ins + mt*16*204;
        #pragma unroll 1
        for (int kt = 0; kt < 25; kt++) {
            int ak = kt*8;
            uint32_t a0 = __float_as_uint(Arow[ g   *204 + ak + tg    ]);
            uint32_t a1 = __float_as_uint(Arow[(g+8)*204 + ak + tg    ]);
            uint32_t a2 = __float_as_uint(Arow[ g   *204 + ak + tg + 4]);
            uint32_t a3 = __float_as_uint(Arow[(g+8)*204 + ak + tg + 4]);
            #pragma unroll
            for (int j = 0; j < 4; j++) {
                int nt = ng*4 + j;
                if (nt < 13) {
                    uint32_t b0 = __float_as_uint(wA[(ak + tg    )*104 + nt*8 + g]);
                    uint32_t b1 = __float_as_uint(wA[(ak + tg + 4)*104 + nt*8 + g]);
                    asm volatile(
                        "mma.sync.aligned.m16n8k8.row.col.f32.tf32.tf32.f32 "
                        "{%0,%1,%2,%3}, {%4,%5,%6,%7}, {%8,%9}, {%0,%1,%2,%3};"
                        : "+f"(acc[j][0]), "+f"(acc[j][1]), "+f"(acc[j][2]), "+f"(acc[j][3])
                        : "r"(a0), "r"(a1), "r"(a2), "r"(a3), "r"(b0), "r"(b1));
                }
            }
        }
        #pragma unroll
        for (int j = 0; j < 4; j++) {
            int nt = ng*4 + j;
            if (nt < 13) {
                int c = nt*8 + tg*2;
                if (c < 100) {
                    nh[rl*108 + c] = to_tf32(tanhf(acc[j][0]));
                    nh[rh*108 + c] = to_tf32(tanhf(acc[j][2]));
                }
                if (c + 1 < 100) {
                    nh[rl*108 + c + 1] = to_tf32(tanhf(acc[j][1]));
                    nh[rh*108 + c + 1] = to_tf32(tanhf(acc[j][3]));
                }
            }
        }
    }
    __syncthreads();
    for (int i = tid; i < 104*104; i += 256) wA[i] = 0.f;
    __syncthreads();
    for (int i = tid; i < 100*100; i += 256) {
        int k = i / 100, n = i % 100;
        wA[k*104 + n] = to_tf32(glu1_w[i]);
    }
    __syncthreads();

    // GEMM2: t = nh @ glu1_w; sigmoid(t + hb); beta partials
    {
        float t[4][4];
        #pragma unroll
        for (int j = 0; j < 4; j++)
            #pragma unroll
            for (int q = 0; q < 4; q++) t[j][q] = 0.f;
        const float* A2 = nh + mt*16*108;
        #pragma unroll 1
        for (int kt = 0; kt < 13; kt++) {
            int ak = kt*8;
            uint32_t a0 = __float_as_uint(A2[ g   *108 + ak + tg    ]);
            uint32_t a1 = __float_as_uint(A2[(g+8)*108 + ak + tg    ]);
            uint32_t a2 = __float_as_uint(A2[ g   *108 + ak + tg + 4]);
            uint32_t a3 = __float_as_uint(A2[(g+8)*108 + ak + tg + 4]);
            #pragma unroll
            for (int j = 0; j < 4; j++) {
                int nt = ng*4 + j;
                if (nt < 13) {
                    uint32_t b0 = __float_as_uint(wA[(ak + tg    )*104 + nt*8 + g]);
                    uint32_t b1 = __float_as_uint(wA[(ak + tg + 4)*104 + nt*8 + g]);
                    asm volatile(
                        "mma.sync.aligned.m16n8k8.row.col.f32.tf32.tf32.f32 "
                        "{%0,%1,%2,%3}, {%4,%5,%6,%7}, {%8,%9}, {%0,%1,%2,%3};"
                        : "+f"(t[j][0]), "+f"(t[j][1]), "+f"(t[j][2]), "+f"(t[j][3])
                        : "r"(a0), "r"(a1), "r"(a2), "r"(a3), "r"(b0), "r"(b1));
                }
            }
        }
        float p_lo = 0.f, p_hi = 0.f;
        #pragma unroll
        for (int j = 0; j < 4; j++) {
            int nt = ng*4 + j;
            if (nt < 13) {
                int c = nt*8 + tg*2;
                if (c < 100) {
                    float s0 = 1.f / (1.f + __expf(-(t[j][0] + hb_s[c])));
                    float s2 = 1.f / (1.f + __expf(-(t[j][2] + hb_s[c])));
                    p_lo = fmaf(s0, w2s[c], p_lo);
                    p_hi = fmaf(s2, w2s[c], p_hi);
                }
                if (c + 1 < 100) {
                    float s1 = 1.f / (1.f + __expf(-(t[j][1] + hb_s[c+1])));
                    float s3 = 1.f / (1.f + __expf(-(t[j][3] + hb_s[c+1])));
                    p_lo = fmaf(s1, w2s[c+1], p_lo);
                    p_hi = fmaf(s3, w2s[c+1], p_hi);
                }
            }
        }
        p_lo += __shfl_xor_sync(0xffffffffu, p_lo, 1);
        p_lo += __shfl_xor_sync(0xffffffffu, p_lo, 2);
        p_hi += __shfl_xor_sync(0xffffffffu, p_hi, 1);
        p_hi += __shfl_xor_sync(0xffffffffu, p_hi, 2);
        if (tg == 0) {
            red[rl*4 + ng] = p_lo;
            red[rh*4 + ng] = p_hi;
        }
    }
    __syncthreads();
    if (tid < 32) {
        float s = red[tid*4] + red[tid*4+1] + red[tid*4+2] + red[tid*4+3];
        beta_s[tid] = s * mask[b*Ldim + lbase + tid];
    }
    __syncthreads();

    if (tid < Dn) {
        float sel = 0.f;
        #pragma unroll 8
        for (int r = 0; r < 32; r++)
            sel = fmaf(beta_s[r], ins[r*204 + 100 + tid], sel);
        g_selpart[blockIdx.x*Dn + tid] = sel;
    }
}

// ---------------- K6a: score (tf32 mma, 64-row batch tile) ------------------
#define SC_EMB  6656          // after sel_s 64*104
#define SC_TOT  (6656 + 128*104)   // 19968 floats
__global__ __launch_bounds__(256) void k_score(
    const float* __restrict__ emb, float* __restrict__ out)
{
    extern __shared__ float sm[];
    float* sel_s = sm;
    float* emb_s = sm + SC_EMB;
    int n0 = blockIdx.x * 128, b0 = blockIdx.y * 64;
    int tid = threadIdx.x;
    int lane = tid & 31, warp = tid >> 5;

    for (int idx = tid; idx < 64*25; idx += 256) {
        int r = idx / 25, c4 = (idx % 25) * 4;
        int bb = b0 + r;
        float4 v0 = *(const float4*)(g_selpart + (2*bb)*Dn + c4);
        float4 v1 = *(const float4*)(g_selpart + (2*bb+1)*Dn + c4);
        float* d = sel_s + r*104 + c4;
        d[0] = to_tf32(v0.x + v1.x); d[1] = to_tf32(v0.y + v1.y);
        d[2] = to_tf32(v0.z + v1.z); d[3] = to_tf32(v0.w + v1.w);
    }
    if (tid < 64) {
        float* d = sel_s + tid*104 + 100;
        d[0] = 0.f; d[1] = 0.f; d[2] = 0.f; d[3] = 0.f;
    }
    for (int idx = tid; idx < 128*25; idx += 256) {
        int r = idx / 25, c4 = (idx % 25) * 4;
        int n = n0 + r;
        float4 v = make_float4(0.f,0.f,0.f,0.f);
        if (n < NOUT) v = *(const float4*)(emb + (size_t)(n + 1)*Dn + c4);
        float* d = emb_s + r*104 + c4;
        d[0] = to_tf32(v.x); d[1] = to_tf32(v.y);
        d[2] = to_tf32(v.z); d[3] = to_tf32(v.w);
    }
    if (tid < 128) {
        float* d = emb_s + tid*104 + 100;
        d[0] = 0.f; d[1] = 0.f; d[2] = 0.f; d[3] = 0.f;
    }
    __syncthreads();

    int g = lane >> 2, tg = lane & 3;
    int mt = warp & 3;
    int nb = warp >> 2;
    const float* Arow = sel_s + mt*16*104;

    float acc[8][4];
    #pragma unroll
    for (int j = 0; j < 8; j++)
        #pragma unroll
        for (int q = 0; q < 4; q++) acc[j][q] = 0.f;

    #pragma unroll 1
    for (int kt = 0; kt < 13; kt++) {
        int ak = kt*8;
        uint32_t a0 = __float_as_uint(Arow[ g   *104 + ak + tg    ]);
        uint32_t a1 = __float_as_uint(Arow[(g+8)*104 + ak + tg    ]);
        uint32_t a2 = __float_as_uint(Arow[ g   *104 + ak + tg + 4]);
        uint32_t a3 = __float_as_uint(Arow[(g+8)*104 + ak + tg + 4]);
        #pragma unroll
        for (int j = 0; j < 8; j++) {
            int nt = nb*8 + j;
            uint32_t bb0 = __float_as_uint(emb_s[(nt*8 + g)*104 + ak + tg    ]);
            uint32_t bb1 = __float_as_uint(emb_s[(nt*8 + g)*104 + ak + tg + 4]);
            asm volatile(
                "mma.sync.aligned.m16n8k8.row.col.f32.tf32.tf32.f32 "
                "{%0,%1,%2,%3}, {%4,%5,%6,%7}, {%8,%9}, {%0,%1,%2,%3};"
                : "+f"(acc[j][0]), "+f"(acc[j][1]), "+f"(acc[j][2]), "+f"(acc[j][3])
                : "r"(a0), "r"(a1), "r"(a2), "r"(a3), "r"(bb0), "r"(bb1));
        }
    }

    int row_lo = b0 + mt*16 + g;
    int row_hi = row_lo + 8;
    float rmax_lo = -3.0e38f, rmax_hi = -3.0e38f;
    #pragma unroll
    for (int j = 0; j < 8; j++) {
        int nt = nb*8 + j;
        int ncol = n0 + nt*8 + tg*2;
        if (ncol < NOUT) {
            out[(size_t)row_lo*NOUT + ncol] = acc[j][0];
            out[(size_t)row_hi*NOUT + ncol] = acc[j][2];
            rmax_lo = fmaxf(rmax_lo, acc[j][0]);
            rmax_hi = fmaxf(rmax_hi, acc[j][2]);
        }
        if (ncol + 1 < NOUT) {
            out[(size_t)row_lo*NOUT + ncol + 1] = acc[j][1];
            out[(size_t)row_hi*NOUT + ncol + 1] = acc[j][3];
            rmax_lo = fmaxf(rmax_lo, acc[j][1]);
            rmax_hi = fmaxf(rmax_hi, acc[j][3]);
        }
    }
    rmax_lo = fmaxf(rmax_lo, __shfl_xor_sync(0xffffffffu, rmax_lo, 1));
    rmax_lo = fmaxf(rmax_lo, __shfl_xor_sync(0xffffffffu, rmax_lo, 2));
    rmax_hi = fmaxf(rmax_hi, __shfl_xor_sync(0xffffffffu, rmax_hi, 1));
    rmax_hi = fmaxf(rmax_hi, __shfl_xor_sync(0xffffffffu, rmax_hi, 2));
    if (tg == 0) {
        atomicMax(&g_rmaxbits[row_lo], fkey(rmax_lo));
        atomicMax(&g_rmaxbits[row_hi], fkey(rmax_hi));
    }
}

// ---------------- K6b: per-chunk sum of exp ----------------
__global__ __launch_bounds__(256) void k_expsum(const float* __restrict__ out)
{
    int b = blockIdx.y, chunk = blockIdx.x, tid = threadIdx.x;
    int start = chunk * CHUNKSZ;
    int end = start + CHUNKSZ; if (end > NOUT) end = NOUT;
    float m = funkey(g_rmaxbits[b]);
    float s = 0.f;
    for (int n = start + tid; n < end; n += 256)
        s += fexp(out[(size_t)b*NOUT + n] - m);
    __shared__ float red[256];
    red[tid] = s;
    __syncthreads();
    for (int st = 128; st > 0; st >>= 1) {
        if (tid < st) red[tid] += red[tid + st];
        __syncthreads();
    }
    if (tid == 0) g_rpart[b*NCHUNK + chunk] = red[0];
}

// ---------------- K6c: exp + scale ----------------
__global__ __launch_bounds__(256) void k_scale(float* __restrict__ out)
{
    int b = blockIdx.y;
    int n = blockIdx.x * 256 + threadIdx.x;
    if (n < NOUT) {
        float ssum = 0.f;
        #pragma unroll
        for (int j = 0; j < NCHUNK; j++) ssum += g_rpart[b*NCHUNK + j];
        float m = funkey(g_rmaxbits[b]);
        float inv = __fdividef(1.f, ssum);
        size_t idx = (size_t)b*NOUT + n;
        out[idx] = fexp(out[idx] - m) * inv;
    }
}

// ---------------- launch ----------------
extern "C" void kernel_launch(void* const* d_in, const int* in_sizes, int n_in,
                              void* d_out, int out_size)
{
    const int*   alias_inputs = (const int*)  d_in[0];
    const int*   items        = (const int*)  d_in[1];
    const int*   adj          = (const int*)  d_in[2];
    const float* mask_item    = (const float*)d_in[3];
    const int*   seq_features = (const int*)  d_in[4];
    const int*   adj_all      = (const int*)  d_in[5];
    const float* num_w        = (const float*)d_in[6];
    const float* emb          = (const float*)d_in[7];
    const float* pos_emb      = (const float*)d_in[8];
    const float* a0           = (const float*)d_in[9];
    const float* a1           = (const float*)d_in[10];
    const float* a2           = (const float*)d_in[11];
    const float* a3           = (const float*)d_in[12];
    const float* g_w1         = (const float*)d_in[13];
    const float* g_w2         = (const float*)d_in[14];
    const float* g_w3         = (const float*)d_in[15];
    const float* w_1          = (const float*)d_in[16];
    const float* w_2          = (const float*)d_in[17];
    const float* glu1_w       = (const float*)d_in[18];
    const float* glu1_b       = (const float*)d_in[19];
    const float* glu2_w       = (const float*)d_in[20];
    const float* glu2_b       = (const float*)d_in[21];
    float* out = (float*)d_out;

    static cudaStream_t s2 = nullptr;
    static cudaEvent_t ev_fork = nullptr, ev_join = nullptr;
    static bool attr_done = false;
    if (!s2) {
        cudaStreamCreateWithFlags(&s2, cudaStreamNonBlocking);
        cudaEventCreateWithFlags(&ev_fork, cudaEventDisableTiming);
        cudaEventCreateWithFlags(&ev_join, cudaEventDisableTiming);
    }

    const int GSMEM = GT_TOT * 4;                  // ~86.3 KB
    const int CSMEM = CB_TOT * 4;                  // ~110.2 KB
    const int NSMEM = NS_TOT * 4;                  // ~124.6 KB
    const int SSMEM = SC_TOT * 4;                  // ~79.9 KB
    if (!attr_done) {
        cudaFuncSetAttribute(k_global,  cudaFuncAttributeMaxDynamicSharedMemorySize, GSMEM);
        cudaFuncSetAttribute(k_combseq, cudaFuncAttributeMaxDynamicSharedMemorySize, CSMEM);
        cudaFuncSetAttribute(k_nhsel,   cudaFuncAttributeMaxDynamicSharedMemorySize, NSMEM);
        cudaFuncSetAttribute(k_score,   cudaFuncAttributeMaxDynamicSharedMemorySize, SSMEM);
        attr_done = true;
    }

    k_init   <<<1, 256>>>();
    cudaEventRecord(ev_fork, 0);
    cudaStreamWaitEvent(s2, ev_fork, 0);
    k_local  <<<Bn*2, 256, 0, s2>>>(items, adj, emb, a0, a1, a2, a3);
    k_global <<<Bn*2, 256, GSMEM>>>(items, adj_all, num_w, emb, g_w1, g_w2,
                                    seq_features, mask_item);
    cudaEventRecord(ev_join, s2);
    cudaStreamWaitEvent(0, ev_join, 0);
    k_combseq<<<Bn, 256, CSMEM>>>(g_w3, alias_inputs, mask_item, glu2_w, glu2_b);
    k_nhsel  <<<(Bn*Ldim)/32, 256, NSMEM>>>(pos_emb, w_1, glu1_w, glu1_b, w_2, mask_item);
    dim3 gs((NOUT + 127)/128, Bn/64);
    k_score  <<<gs, 256, SSMEM>>>(emb, out);
    dim3 ge(NCHUNK, Bn);
    k_expsum <<<ge, 256>>>(out);
    dim3 gn((NOUT + 255)/256, Bn);
    k_scale  <<<gn, 256>>>(out);
}